// round 9
// baseline (speedup 1.0000x reference)
#include <cuda_runtime.h>
#include <cuda_bf16.h>
#include <math.h>
#include <stdint.h>

#define N_NODES  20000
#define N_EDGES  320000
#define N_GRAPHS 1000

// ---------------- static device scratch (no allocations allowed) ----------------
__device__ float    g_xl[N_NODES * 256];
__device__ float    g_xr[N_NODES * 256];
__device__ float    g_hA[N_NODES * 256];
__device__ uint16_t g_ahi[N_NODES * 256];
__device__ uint16_t g_alo[N_NODES * 256];
__device__ uint16_t g_whL[256 * 256];
__device__ uint16_t g_wlL[256 * 256];
__device__ uint16_t g_whR[256 * 256];
__device__ uint16_t g_wlR[256 * 256];
__device__ int      g_deg[N_NODES];
__device__ int      g_rowptr[N_NODES + 1];
__device__ int      g_cursor[N_NODES];
__device__ int      g_csr_src[N_EDGES];
__device__ float4   g_csr_ea[N_EDGES];
__device__ float    g_sums[N_GRAPHS * 64];
__device__ int      g_cnt[N_GRAPHS];

// ---------------- utility kernels ----------------
__global__ void zero_i32(int* p, int n) {
    int i = blockIdx.x * blockDim.x + threadIdx.x;
    if (i < n) p[i] = 0;
}
__global__ void zero_f32(float* p, int n) {
    int i = blockIdx.x * blockDim.x + threadIdx.x;
    if (i < n) p[i] = 0.f;
}
__global__ void hist_k(const int* __restrict__ dst, int* __restrict__ deg) {
    int e = blockIdx.x * blockDim.x + threadIdx.x;
    if (e < N_EDGES) atomicAdd(&deg[dst[e]], 1);
}

__global__ void scan_k(const int* __restrict__ deg, int* __restrict__ rowptr,
                       int* __restrict__ cursor) {
    __shared__ int sh[1024];
    const int CH = 20;
    int t = threadIdx.x;
    int base = t * CH;
    int loc[CH];
    int s = 0;
    #pragma unroll
    for (int i = 0; i < CH; i++) {
        int idx = base + i;
        int v = (idx < N_NODES) ? deg[idx] : 0;
        loc[i] = s;
        s += v;
    }
    sh[t] = s;
    __syncthreads();
    for (int off = 1; off < 1024; off <<= 1) {
        int v = (t >= off) ? sh[t - off] : 0;
        __syncthreads();
        sh[t] += v;
        __syncthreads();
    }
    int pre = (t > 0) ? sh[t - 1] : 0;
    #pragma unroll
    for (int i = 0; i < CH; i++) {
        int idx = base + i;
        if (idx < N_NODES) {
            int v = pre + loc[i];
            rowptr[idx] = v;
            cursor[idx] = v;
        }
    }
    if (t == 1023) rowptr[N_NODES] = sh[1023];
}

__global__ void scatter_k(const int* __restrict__ src, const int* __restrict__ dst,
                          const float4* __restrict__ ea, int* __restrict__ cursor,
                          int* __restrict__ csr_src, float4* __restrict__ csr_ea) {
    int e = blockIdx.x * blockDim.x + threadIdx.x;
    if (e < N_EDGES) {
        int p = atomicAdd(&cursor[dst[e]], 1);
        csr_src[p] = src[e];
        csr_ea[p] = ea[e];
    }
}

// dual W split: both L and R weights, W[K][Nc] fp32 -> transposed [Nc][K] bf16 hi/lo
__global__ void splitW_dual(const float* __restrict__ WL, const float* __restrict__ WR,
                            __nv_bfloat16* __restrict__ hiL, __nv_bfloat16* __restrict__ loL,
                            __nv_bfloat16* __restrict__ hiR, __nv_bfloat16* __restrict__ loR,
                            int K, int Nc) {
    int i = blockIdx.x * blockDim.x + threadIdx.x;
    if (i < K * Nc) {
        int k = i / Nc, n = i - k * Nc;
        float v = WL[i];
        __nv_bfloat16 h = __float2bfloat16(v);
        hiL[(size_t)n * K + k] = h;
        loL[(size_t)n * K + k] = __float2bfloat16(v - __bfloat162float(h));
        v = WR[i];
        h = __float2bfloat16(v);
        hiR[(size_t)n * K + k] = h;
        loR[(size_t)n * K + k] = __float2bfloat16(v - __bfloat162float(h));
    }
}

// ---------------- layer-1 dual GEMM (K=12 -> 256 for both Wl and Wr) ----------------
__global__ void gemm_k12_dual(const float* __restrict__ x,
                              const float* __restrict__ WL, const float* __restrict__ bL,
                              const float* __restrict__ WR, const float* __restrict__ bR,
                              float* __restrict__ xl, float* __restrict__ xr) {
    __shared__ float WsL[12 * 256];
    __shared__ float WsR[12 * 256];
    __shared__ float xs[32 * 12];
    int tid = threadIdx.x;
    int r0 = blockIdx.x * 32;
    for (int i = tid; i < 12 * 256; i += 256) {
        WsL[i] = WL[i];
        WsR[i] = WR[i];
    }
    for (int i = tid; i < 32 * 12; i += 256) {
        int r = r0 + i / 12;
        xs[i] = (r < N_NODES) ? x[(size_t)r * 12 + (i % 12)] : 0.f;
    }
    __syncthreads();
    float bbL = bL[tid], bbR = bR[tid];
    for (int r = 0; r < 32; r++) {
        int gr = r0 + r;
        if (gr >= N_NODES) break;
        float accL = bbL, accR = bbR;
        #pragma unroll
        for (int k = 0; k < 12; k++) {
            float xv = xs[r * 12 + k];
            accL += xv * WsL[k * 256 + tid];
            accR += xv * WsR[k * 256 + tid];
        }
        xl[(size_t)gr * 256 + tid] = accL;
        xr[(size_t)gr * 256 + tid] = accR;
    }
}

// ---------------- bf16 mma.sync GEMM with pre-split hi/lo (3-term) ----------------
__device__ __forceinline__ uint32_t smem_u32(const void* p) {
    uint32_t a;
    asm("{ .reg .u64 t; cvta.to.shared.u64 t, %1; cvt.u32.u64 %0, t; }" : "=r"(a) : "l"(p));
    return a;
}
#define LDSM_X4(r0, r1, r2, r3, addr) \
    asm volatile("ldmatrix.sync.aligned.m8n8.x4.shared.b16 {%0,%1,%2,%3}, [%4];" \
                 : "=r"(r0), "=r"(r1), "=r"(r2), "=r"(r3) : "r"(addr))
#define LDSM_X2(r0, r1, addr) \
    asm volatile("ldmatrix.sync.aligned.m8n8.x2.shared.b16 {%0,%1}, [%2];" \
                 : "=r"(r0), "=r"(r1) : "r"(addr))
__device__ __forceinline__ void mma_bf16(float* d, uint32_t a0, uint32_t a1,
                                         uint32_t a2, uint32_t a3,
                                         uint32_t b0, uint32_t b1) {
    asm volatile(
        "mma.sync.aligned.m16n8k16.row.col.f32.bf16.bf16.f32 "
        "{%0,%1,%2,%3},{%4,%5,%6,%7},{%8,%9},{%0,%1,%2,%3};"
        : "+f"(d[0]), "+f"(d[1]), "+f"(d[2]), "+f"(d[3])
        : "r"(a0), "r"(a1), "r"(a2), "r"(a3), "r"(b0), "r"(b1));
}

// C[M,Ncols] = A @ W + bias. BM=128, BN=64, BK=32. 256 threads = 8 warps.
__global__ __launch_bounds__(256) void gemm_bf16(
    const __nv_bfloat16* __restrict__ Ahi, const __nv_bfloat16* __restrict__ Alo,
    const __nv_bfloat16* __restrict__ BhiT, const __nv_bfloat16* __restrict__ BloT,
    const float* __restrict__ bias, float* __restrict__ C, int M, int K, int Ncols) {
    const int SA = 40;
    __shared__ __align__(16) uint16_t As_h[128 * 40];
    __shared__ __align__(16) uint16_t As_l[128 * 40];
    __shared__ __align__(16) uint16_t Bs_h[64 * 40];
    __shared__ __align__(16) uint16_t Bs_l[64 * 40];

    int tid = threadIdx.x, lane = tid & 31, warp = tid >> 5;
    int warpM = warp & 3, warpN = warp >> 2;
    int row0 = blockIdx.y * 128, col0 = blockIdx.x * 64;

    float acc[2][4][4];
    #pragma unroll
    for (int mt = 0; mt < 2; mt++)
        #pragma unroll
        for (int nt = 0; nt < 4; nt++)
            #pragma unroll
            for (int i = 0; i < 4; i++) acc[mt][nt][i] = 0.f;

    uint32_t aadH[2], aadL[2], badH[4], badL[4];
    {
        int ar = (lane & 7) + ((lane >> 3) & 1) * 8;
        int ac = (lane >> 4) * 8;
        #pragma unroll
        for (int mt = 0; mt < 2; mt++) {
            int r = warpM * 32 + mt * 16 + ar;
            aadH[mt] = smem_u32(As_h) + (uint32_t)(r * SA + ac) * 2;
            aadL[mt] = smem_u32(As_l) + (uint32_t)(r * SA + ac) * 2;
        }
        int l16 = lane & 15;
        int bn = l16 & 7;
        int bc = ((l16 >> 3) & 1) * 8;
        #pragma unroll
        for (int nt = 0; nt < 4; nt++) {
            int n = warpN * 32 + nt * 8 + bn;
            badH[nt] = smem_u32(Bs_h) + (uint32_t)(n * SA + bc) * 2;
            badL[nt] = smem_u32(Bs_l) + (uint32_t)(n * SA + bc) * 2;
        }
    }

    for (int k0 = 0; k0 < K; k0 += 32) {
        #pragma unroll
        for (int it = 0; it < 2; it++) {
            int idx = tid + it * 256;
            int r = idx >> 2, sk = (idx & 3) * 8;
            int grow = row0 + r;
            uint4 vh = make_uint4(0, 0, 0, 0), vl = make_uint4(0, 0, 0, 0);
            if (grow < M) {
                size_t off = (size_t)grow * K + k0 + sk;
                vh = *(const uint4*)(Ahi + off);
                vl = *(const uint4*)(Alo + off);
            }
            *(uint4*)&As_h[r * SA + sk] = vh;
            *(uint4*)&As_l[r * SA + sk] = vl;
        }
        {
            int r = tid >> 2, sk = (tid & 3) * 8;
            size_t off = (size_t)(col0 + r) * K + k0 + sk;
            *(uint4*)&Bs_h[r * SA + sk] = *(const uint4*)(BhiT + off);
            *(uint4*)&Bs_l[r * SA + sk] = *(const uint4*)(BloT + off);
        }
        __syncthreads();

        #pragma unroll
        for (int ks = 0; ks < 32; ks += 16) {
            uint32_t kb = ks * 2;
            uint32_t ah[2][4], al[2][4], bh[4][2], bl[4][2];
            #pragma unroll
            for (int mt = 0; mt < 2; mt++) {
                LDSM_X4(ah[mt][0], ah[mt][1], ah[mt][2], ah[mt][3], aadH[mt] + kb);
                LDSM_X4(al[mt][0], al[mt][1], al[mt][2], al[mt][3], aadL[mt] + kb);
            }
            #pragma unroll
            for (int nt = 0; nt < 4; nt++) {
                LDSM_X2(bh[nt][0], bh[nt][1], badH[nt] + kb);
                LDSM_X2(bl[nt][0], bl[nt][1], badL[nt] + kb);
            }
            #pragma unroll
            for (int mt = 0; mt < 2; mt++)
                #pragma unroll
                for (int nt = 0; nt < 4; nt++) {
                    mma_bf16(acc[mt][nt], ah[mt][0], ah[mt][1], ah[mt][2], ah[mt][3],
                             bl[nt][0], bl[nt][1]);
                    mma_bf16(acc[mt][nt], al[mt][0], al[mt][1], al[mt][2], al[mt][3],
                             bh[nt][0], bh[nt][1]);
                    mma_bf16(acc[mt][nt], ah[mt][0], ah[mt][1], ah[mt][2], ah[mt][3],
                             bh[nt][0], bh[nt][1]);
                }
        }
        __syncthreads();
    }

    int g = lane >> 2, tg = lane & 3;
    #pragma unroll
    for (int nt = 0; nt < 4; nt++) {
        int col = col0 + warpN * 32 + nt * 8 + 2 * tg;
        float2 bv = *(const float2*)(bias + col);
        #pragma unroll
        for (int mt = 0; mt < 2; mt++) {
            int r = row0 + warpM * 32 + mt * 16 + g;
            if (r < M) {
                float2 v = make_float2(acc[mt][nt][0] + bv.x, acc[mt][nt][1] + bv.y);
                *(float2*)(C + (size_t)r * Ncols + col) = v;
            }
            if (r + 8 < M) {
                float2 v = make_float2(acc[mt][nt][2] + bv.x, acc[mt][nt][3] + bv.y);
                *(float2*)(C + (size_t)(r + 8) * Ncols + col) = v;
            }
        }
    }
}

// ---------------- fused edge aggregation ----------------
// one warp per (node, head), lane owns 2 contiguous channels.
// No max-subtraction (logits O(1)); 8-edge unroll (8 independent load chains).
template <int H, bool OUT_BF16>
__global__ void edge_agg(const int* __restrict__ rowptr, const int* __restrict__ csr_src,
                         const float4* __restrict__ csr_ea,
                         const float* __restrict__ xl, const float* __restrict__ xr,
                         const float* __restrict__ We, const float* __restrict__ att,
                         const float* __restrict__ bias, float* __restrict__ out_f32,
                         __nv_bfloat16* __restrict__ out_hi, __nv_bfloat16* __restrict__ out_lo) {
    const int D = H * 64;
    int w = (blockIdx.x * blockDim.x + threadIdx.x) >> 5;
    int lane = threadIdx.x & 31;
    int n = w / H;
    int h = w - n * H;
    if (n >= N_NODES) return;

    int c = h * 64 + 2 * lane;
    float2 xrv = *(const float2*)(xr + (size_t)n * D + c);
    float2 atv = *(const float2*)(att + c);
    float2 wev[4];
    #pragma unroll
    for (int f = 0; f < 4; f++) wev[f] = *(const float2*)(We + f * D + c);

    float s0 = 0.f, s1 = 0.f;
    float a00 = 0.f, a01 = 0.f, a10 = 0.f, a11 = 0.f;
    int beg = rowptr[n], end = rowptr[n + 1];

    int i = beg;
    for (; i + 7 < end; i += 8) {
        int sn[8];
        float4 e[8];
        float2 xv[8];
        #pragma unroll
        for (int j = 0; j < 8; j++) sn[j] = csr_src[i + j];
        #pragma unroll
        for (int j = 0; j < 8; j++) e[j] = csr_ea[i + j];
        #pragma unroll
        for (int j = 0; j < 8; j++) xv[j] = *(const float2*)(xl + (size_t)sn[j] * D + c);

        float t[8];
        #pragma unroll
        for (int j = 0; j < 8; j++) {
            float z0 = xv[j].x + xrv.x + e[j].x * wev[0].x + e[j].y * wev[1].x
                       + e[j].z * wev[2].x + e[j].w * wev[3].x;
            float z1 = xv[j].y + xrv.y + e[j].x * wev[0].y + e[j].y * wev[1].y
                       + e[j].z * wev[2].y + e[j].w * wev[3].y;
            z0 = z0 > 0.f ? z0 : 0.2f * z0;
            z1 = z1 > 0.f ? z1 : 0.2f * z1;
            t[j] = z0 * atv.x + z1 * atv.y;
        }
        #pragma unroll
        for (int o = 16; o > 0; o >>= 1) {
            #pragma unroll
            for (int j = 0; j < 8; j++) t[j] += __shfl_xor_sync(0xFFFFFFFFu, t[j], o);
        }
        #pragma unroll
        for (int j = 0; j < 8; j++) {
            float p = __expf(t[j]);
            if (j & 1) { s1 += p; a10 += p * xv[j].x; a11 += p * xv[j].y; }
            else       { s0 += p; a00 += p * xv[j].x; a01 += p * xv[j].y; }
        }
    }
    for (; i < end; i++) {
        int sn = csr_src[i];
        float4 eav = csr_ea[i];
        float2 xv = *(const float2*)(xl + (size_t)sn * D + c);
        float z0 = xv.x + xrv.x + eav.x * wev[0].x + eav.y * wev[1].x + eav.z * wev[2].x + eav.w * wev[3].x;
        float z1 = xv.y + xrv.y + eav.x * wev[0].y + eav.y * wev[1].y + eav.z * wev[2].y + eav.w * wev[3].y;
        z0 = z0 > 0.f ? z0 : 0.2f * z0;
        z1 = z1 > 0.f ? z1 : 0.2f * z1;
        float t = z0 * atv.x + z1 * atv.y;
        #pragma unroll
        for (int o = 16; o > 0; o >>= 1) t += __shfl_xor_sync(0xFFFFFFFFu, t, o);
        float p = __expf(t);
        s0 += p; a00 += p * xv.x; a01 += p * xv.y;
    }
    float s = s0 + s1;
    float a0 = a00 + a10;
    float a1 = a01 + a11;

    float inv = 1.f / (s + 1e-16f);
    float2 bv = *(const float2*)(bias + c);
    float r0 = a0 * inv + bv.x;
    float r1 = a1 * inv + bv.y;
    if (OUT_BF16) {
        r0 = r0 > 0.f ? r0 : expm1f(r0);
        r1 = r1 > 0.f ? r1 : expm1f(r1);
        __nv_bfloat16 h0 = __float2bfloat16(r0);
        __nv_bfloat16 h1 = __float2bfloat16(r1);
        __nv_bfloat16 l0 = __float2bfloat16(r0 - __bfloat162float(h0));
        __nv_bfloat16 l1 = __float2bfloat16(r1 - __bfloat162float(h1));
        __nv_bfloat162 hv; hv.x = h0; hv.y = h1;
        __nv_bfloat162 lv; lv.x = l0; lv.y = l1;
        *(__nv_bfloat162*)(out_hi + (size_t)n * D + c) = hv;
        *(__nv_bfloat162*)(out_lo + (size_t)n * D + c) = lv;
    } else {
        *(float2*)(out_f32 + (size_t)n * D + c) = make_float2(r0, r1);
    }
}

// ---------------- global mean pool ----------------
__global__ void pool_k(const float* __restrict__ h, const int* __restrict__ batch,
                       float* __restrict__ sums, int* __restrict__ cnt) {
    int idx = blockIdx.x * blockDim.x + threadIdx.x;
    if (idx >= N_NODES * 64) return;
    int n = idx >> 6;
    int ch = idx & 63;
    int g = batch[n];
    atomicAdd(&sums[g * 64 + ch], h[idx]);
    if (ch == 0) atomicAdd(&cnt[g], 1);
}

// ---------------- MLP head ----------------
__global__ void mlp_k(const float* __restrict__ sums, const int* __restrict__ cnt,
                      const float* __restrict__ mW1, const float* __restrict__ mb1,
                      const float* __restrict__ mW2, const float* __restrict__ mb2,
                      const float* __restrict__ mW3, const float* __restrict__ mb3,
                      float* __restrict__ out) {
    __shared__ float gv[64];
    __shared__ float h1[32];
    __shared__ float h2[16];
    int g = blockIdx.x, t = threadIdx.x;
    float cf = fmaxf((float)cnt[g], 1.f);
    gv[t] = sums[g * 64 + t] / cf;
    __syncthreads();
    if (t < 32) {
        float a = mb1[t];
        #pragma unroll
        for (int k = 0; k < 64; k++) a += gv[k] * mW1[k * 32 + t];
        h1[t] = fmaxf(a, 0.f);
    }
    __syncthreads();
    if (t < 16) {
        float a = mb2[t];
        #pragma unroll
        for (int k = 0; k < 32; k++) a += h1[k] * mW2[k * 16 + t];
        h2[t] = fmaxf(a, 0.f);
    }
    __syncthreads();
    if (t < 4) {
        float a = mb3[t];
        #pragma unroll
        for (int k = 0; k < 16; k++) a += h2[k] * mW3[k * 4 + t];
        out[g * 4 + t] = a;
    }
}

// ---------------- launch ----------------
extern "C" void kernel_launch(void* const* d_in, const int* in_sizes, int n_in,
                              void* d_out, int out_size) {
    (void)in_sizes; (void)n_in; (void)out_size;
    const float* x     = (const float*)d_in[0];
    const int*   ei    = (const int*)d_in[1];
    const float* ea    = (const float*)d_in[2];
    const int*   batch = (const int*)d_in[3];
    const float* Wl1 = (const float*)d_in[4],  *bl1 = (const float*)d_in[5];
    const float* Wr1 = (const float*)d_in[6],  *br1 = (const float*)d_in[7];
    const float* We1 = (const float*)d_in[8],  *att1 = (const float*)d_in[9],  *bias1 = (const float*)d_in[10];
    const float* Wl2 = (const float*)d_in[11], *bl2 = (const float*)d_in[12];
    const float* Wr2 = (const float*)d_in[13], *br2 = (const float*)d_in[14];
    const float* We2 = (const float*)d_in[15], *att2 = (const float*)d_in[16], *bias2 = (const float*)d_in[17];
    const float* Wl3 = (const float*)d_in[18], *bl3 = (const float*)d_in[19];
    const float* Wr3 = (const float*)d_in[20], *br3 = (const float*)d_in[21];
    const float* We3 = (const float*)d_in[22], *att3 = (const float*)d_in[23], *bias3 = (const float*)d_in[24];
    const float* mW1 = (const float*)d_in[25], *mb1 = (const float*)d_in[26];
    const float* mW2 = (const float*)d_in[27], *mb2 = (const float*)d_in[28];
    const float* mW3 = (const float*)d_in[29], *mb3 = (const float*)d_in[30];
    float* out = (float*)d_out;

    const int* srcp = ei;
    const int* dstp = ei + N_EDGES;

    float *xl, *xr, *hA, *sums;
    int *deg, *rowptr, *cursor, *csr_src, *cnt;
    float4* csr_ea;
    __nv_bfloat16 *ahi, *alo, *whL, *wlL, *whR, *wlR;
    cudaGetSymbolAddress((void**)&xl, g_xl);
    cudaGetSymbolAddress((void**)&xr, g_xr);
    cudaGetSymbolAddress((void**)&hA, g_hA);
    cudaGetSymbolAddress((void**)&sums, g_sums);
    cudaGetSymbolAddress((void**)&deg, g_deg);
    cudaGetSymbolAddress((void**)&rowptr, g_rowptr);
    cudaGetSymbolAddress((void**)&cursor, g_cursor);
    cudaGetSymbolAddress((void**)&csr_src, g_csr_src);
    cudaGetSymbolAddress((void**)&csr_ea, g_csr_ea);
    cudaGetSymbolAddress((void**)&cnt, g_cnt);
    cudaGetSymbolAddress((void**)&ahi, g_ahi);
    cudaGetSymbolAddress((void**)&alo, g_alo);
    cudaGetSymbolAddress((void**)&whL, g_whL);
    cudaGetSymbolAddress((void**)&wlL, g_wlL);
    cudaGetSymbolAddress((void**)&whR, g_whR);
    cudaGetSymbolAddress((void**)&wlR, g_wlR);

    // launches 1-4: CSR by destination (shared by all 3 layers)
    zero_i32<<<(N_NODES + 255) / 256, 256>>>(deg, N_NODES);
    hist_k<<<(N_EDGES + 255) / 256, 256>>>(dstp, deg);
    scan_k<<<1, 1024>>>(deg, rowptr, cursor);
    scatter_k<<<(N_EDGES + 255) / 256, 256>>>(srcp, dstp, (const float4*)ea, cursor, csr_src, csr_ea);

    // launch 5: layer-1 dual GEMM (xl + xr in one pass)
    gemm_k12_dual<<<(N_NODES + 31) / 32, 256>>>(x, Wl1, bl1, Wr1, br1, xl, xr);

    // launch 6: edge_agg<4> — profiled by ncu (-s 5 -c 1)
    edge_agg<4, true><<<10000, 256>>>(rowptr, csr_src, csr_ea, xl, xr, We1, att1, bias1,
                                      nullptr, ahi, alo);

    // ---- layer 2 (256 -> 256, H=4) ----
    splitW_dual<<<(256 * 256 + 255) / 256, 256>>>(Wl2, Wr2, whL, wlL, whR, wlR, 256, 256);
    gemm_bf16<<<dim3(4, 157), 256>>>(ahi, alo, whL, wlL, bl2, xl, N_NODES, 256, 256);
    gemm_bf16<<<dim3(4, 157), 256>>>(ahi, alo, whR, wlR, br2, xr, N_NODES, 256, 256);
    edge_agg<4, true><<<10000, 256>>>(rowptr, csr_src, csr_ea, xl, xr, We2, att2, bias2,
                                      nullptr, ahi, alo);

    // ---- layer 3 (256 -> 64, H=1, no ELU) ----
    splitW_dual<<<(256 * 64 + 255) / 256, 256>>>(Wl3, Wr3, whL, wlL, whR, wlR, 256, 64);
    gemm_bf16<<<dim3(1, 157), 256>>>(ahi, alo, whL, wlL, bl3, xl, N_NODES, 256, 64);
    gemm_bf16<<<dim3(1, 157), 256>>>(ahi, alo, whR, wlR, br3, xr, N_NODES, 256, 64);
    edge_agg<1, false><<<2500, 256>>>(rowptr, csr_src, csr_ea, xl, xr, We3, att3, bias3,
                                      hA, nullptr, nullptr);

    // ---- global mean pool + MLP head ----
    zero_f32<<<(N_GRAPHS * 64 + 255) / 256, 256>>>(sums, N_GRAPHS * 64);
    zero_i32<<<(N_GRAPHS + 255) / 256, 256>>>(cnt, N_GRAPHS);
    pool_k<<<(N_NODES * 64 + 255) / 256, 256>>>(hA, batch, sums, cnt);
    mlp_k<<<N_GRAPHS, 64>>>(sums, cnt, mW1, mb1, mW2, mb2, mW3, mb3, out);
}

// round 10
// speedup vs baseline: 1.1189x; 1.1189x over previous
#include <cuda_runtime.h>
#include <cuda_bf16.h>
#include <math.h>
#include <stdint.h>

#define N_NODES  20000
#define N_EDGES  320000
#define N_GRAPHS 1000

// ---------------- static device scratch (no allocations allowed) ----------------
__device__ float    g_xl[N_NODES * 256];
__device__ float    g_xr[N_NODES * 256];
__device__ float    g_hA[N_NODES * 256];
__device__ uint16_t g_ahi[N_NODES * 256];
__device__ uint16_t g_alo[N_NODES * 256];
__device__ uint16_t g_whL[256 * 256];
__device__ uint16_t g_wlL[256 * 256];
__device__ uint16_t g_whR[256 * 256];
__device__ uint16_t g_wlR[256 * 256];
__device__ int      g_deg[N_NODES];
__device__ int      g_rowptr[N_NODES + 1];
__device__ int      g_cursor[N_NODES];
__device__ int      g_csr_src[N_EDGES];
__device__ float4   g_csr_ea[N_EDGES];
__device__ float    g_sums[N_GRAPHS * 64];
__device__ int      g_cnt[N_GRAPHS];

// ---------------- utility kernels ----------------
__global__ void zero_i32(int* p, int n) {
    int i = blockIdx.x * blockDim.x + threadIdx.x;
    if (i < n) p[i] = 0;
}
__global__ void zero_f32(float* p, int n) {
    int i = blockIdx.x * blockDim.x + threadIdx.x;
    if (i < n) p[i] = 0.f;
}
__global__ void hist_k(const int* __restrict__ dst, int* __restrict__ deg) {
    int e = blockIdx.x * blockDim.x + threadIdx.x;
    if (e < N_EDGES) atomicAdd(&deg[dst[e]], 1);
}

__global__ void scan_k(const int* __restrict__ deg, int* __restrict__ rowptr,
                       int* __restrict__ cursor) {
    __shared__ int sh[1024];
    const int CH = 20;
    int t = threadIdx.x;
    int base = t * CH;
    int loc[CH];
    int s = 0;
    #pragma unroll
    for (int i = 0; i < CH; i++) {
        int idx = base + i;
        int v = (idx < N_NODES) ? deg[idx] : 0;
        loc[i] = s;
        s += v;
    }
    sh[t] = s;
    __syncthreads();
    for (int off = 1; off < 1024; off <<= 1) {
        int v = (t >= off) ? sh[t - off] : 0;
        __syncthreads();
        sh[t] += v;
        __syncthreads();
    }
    int pre = (t > 0) ? sh[t - 1] : 0;
    #pragma unroll
    for (int i = 0; i < CH; i++) {
        int idx = base + i;
        if (idx < N_NODES) {
            int v = pre + loc[i];
            rowptr[idx] = v;
            cursor[idx] = v;
        }
    }
    if (t == 1023) rowptr[N_NODES] = sh[1023];
}

__global__ void scatter_k(const int* __restrict__ src, const int* __restrict__ dst,
                          const float4* __restrict__ ea, int* __restrict__ cursor,
                          int* __restrict__ csr_src, float4* __restrict__ csr_ea) {
    int e = blockIdx.x * blockDim.x + threadIdx.x;
    if (e < N_EDGES) {
        int p = atomicAdd(&cursor[dst[e]], 1);
        csr_src[p] = src[e];
        csr_ea[p] = ea[e];
    }
}

// dual W split: both L and R weights, W[K][Nc] fp32 -> transposed [Nc][K] bf16 hi/lo
__global__ void splitW_dual(const float* __restrict__ WL, const float* __restrict__ WR,
                            __nv_bfloat16* __restrict__ hiL, __nv_bfloat16* __restrict__ loL,
                            __nv_bfloat16* __restrict__ hiR, __nv_bfloat16* __restrict__ loR,
                            int K, int Nc) {
    int i = blockIdx.x * blockDim.x + threadIdx.x;
    if (i < K * Nc) {
        int k = i / Nc, n = i - k * Nc;
        float v = WL[i];
        __nv_bfloat16 h = __float2bfloat16(v);
        hiL[(size_t)n * K + k] = h;
        loL[(size_t)n * K + k] = __float2bfloat16(v - __bfloat162float(h));
        v = WR[i];
        h = __float2bfloat16(v);
        hiR[(size_t)n * K + k] = h;
        loR[(size_t)n * K + k] = __float2bfloat16(v - __bfloat162float(h));
    }
}

// ---------------- layer-1 dual GEMM (K=12 -> 256 for both Wl and Wr) ----------------
__global__ void gemm_k12_dual(const float* __restrict__ x,
                              const float* __restrict__ WL, const float* __restrict__ bL,
                              const float* __restrict__ WR, const float* __restrict__ bR,
                              float* __restrict__ xl, float* __restrict__ xr) {
    __shared__ float WsL[12 * 256];
    __shared__ float WsR[12 * 256];
    __shared__ float xs[32 * 12];
    int tid = threadIdx.x;
    int r0 = blockIdx.x * 32;
    for (int i = tid; i < 12 * 256; i += 256) {
        WsL[i] = WL[i];
        WsR[i] = WR[i];
    }
    for (int i = tid; i < 32 * 12; i += 256) {
        int r = r0 + i / 12;
        xs[i] = (r < N_NODES) ? x[(size_t)r * 12 + (i % 12)] : 0.f;
    }
    __syncthreads();
    float bbL = bL[tid], bbR = bR[tid];
    for (int r = 0; r < 32; r++) {
        int gr = r0 + r;
        if (gr >= N_NODES) break;
        float accL = bbL, accR = bbR;
        #pragma unroll
        for (int k = 0; k < 12; k++) {
            float xv = xs[r * 12 + k];
            accL += xv * WsL[k * 256 + tid];
            accR += xv * WsR[k * 256 + tid];
        }
        xl[(size_t)gr * 256 + tid] = accL;
        xr[(size_t)gr * 256 + tid] = accR;
    }
}

// ---------------- bf16 mma.sync GEMM with pre-split hi/lo (3-term) ----------------
__device__ __forceinline__ uint32_t smem_u32(const void* p) {
    uint32_t a;
    asm("{ .reg .u64 t; cvta.to.shared.u64 t, %1; cvt.u32.u64 %0, t; }" : "=r"(a) : "l"(p));
    return a;
}
#define LDSM_X4(r0, r1, r2, r3, addr) \
    asm volatile("ldmatrix.sync.aligned.m8n8.x4.shared.b16 {%0,%1,%2,%3}, [%4];" \
                 : "=r"(r0), "=r"(r1), "=r"(r2), "=r"(r3) : "r"(addr))
#define LDSM_X2(r0, r1, addr) \
    asm volatile("ldmatrix.sync.aligned.m8n8.x2.shared.b16 {%0,%1}, [%2];" \
                 : "=r"(r0), "=r"(r1) : "r"(addr))
__device__ __forceinline__ void mma_bf16(float* d, uint32_t a0, uint32_t a1,
                                         uint32_t a2, uint32_t a3,
                                         uint32_t b0, uint32_t b1) {
    asm volatile(
        "mma.sync.aligned.m16n8k16.row.col.f32.bf16.bf16.f32 "
        "{%0,%1,%2,%3},{%4,%5,%6,%7},{%8,%9},{%0,%1,%2,%3};"
        : "+f"(d[0]), "+f"(d[1]), "+f"(d[2]), "+f"(d[3])
        : "r"(a0), "r"(a1), "r"(a2), "r"(a3), "r"(b0), "r"(b1));
}

// C[M,Ncols] = A @ W + bias. BM=128, BN=64, BK=32. 256 threads = 8 warps.
__global__ __launch_bounds__(256) void gemm_bf16(
    const __nv_bfloat16* __restrict__ Ahi, const __nv_bfloat16* __restrict__ Alo,
    const __nv_bfloat16* __restrict__ BhiT, const __nv_bfloat16* __restrict__ BloT,
    const float* __restrict__ bias, float* __restrict__ C, int M, int K, int Ncols) {
    const int SA = 40;
    __shared__ __align__(16) uint16_t As_h[128 * 40];
    __shared__ __align__(16) uint16_t As_l[128 * 40];
    __shared__ __align__(16) uint16_t Bs_h[64 * 40];
    __shared__ __align__(16) uint16_t Bs_l[64 * 40];

    int tid = threadIdx.x, lane = tid & 31, warp = tid >> 5;
    int warpM = warp & 3, warpN = warp >> 2;
    int row0 = blockIdx.y * 128, col0 = blockIdx.x * 64;

    float acc[2][4][4];
    #pragma unroll
    for (int mt = 0; mt < 2; mt++)
        #pragma unroll
        for (int nt = 0; nt < 4; nt++)
            #pragma unroll
            for (int i = 0; i < 4; i++) acc[mt][nt][i] = 0.f;

    uint32_t aadH[2], aadL[2], badH[4], badL[4];
    {
        int ar = (lane & 7) + ((lane >> 3) & 1) * 8;
        int ac = (lane >> 4) * 8;
        #pragma unroll
        for (int mt = 0; mt < 2; mt++) {
            int r = warpM * 32 + mt * 16 + ar;
            aadH[mt] = smem_u32(As_h) + (uint32_t)(r * SA + ac) * 2;
            aadL[mt] = smem_u32(As_l) + (uint32_t)(r * SA + ac) * 2;
        }
        int l16 = lane & 15;
        int bn = l16 & 7;
        int bc = ((l16 >> 3) & 1) * 8;
        #pragma unroll
        for (int nt = 0; nt < 4; nt++) {
            int n = warpN * 32 + nt * 8 + bn;
            badH[nt] = smem_u32(Bs_h) + (uint32_t)(n * SA + bc) * 2;
            badL[nt] = smem_u32(Bs_l) + (uint32_t)(n * SA + bc) * 2;
        }
    }

    for (int k0 = 0; k0 < K; k0 += 32) {
        #pragma unroll
        for (int it = 0; it < 2; it++) {
            int idx = tid + it * 256;
            int r = idx >> 2, sk = (idx & 3) * 8;
            int grow = row0 + r;
            uint4 vh = make_uint4(0, 0, 0, 0), vl = make_uint4(0, 0, 0, 0);
            if (grow < M) {
                size_t off = (size_t)grow * K + k0 + sk;
                vh = *(const uint4*)(Ahi + off);
                vl = *(const uint4*)(Alo + off);
            }
            *(uint4*)&As_h[r * SA + sk] = vh;
            *(uint4*)&As_l[r * SA + sk] = vl;
        }
        {
            int r = tid >> 2, sk = (tid & 3) * 8;
            size_t off = (size_t)(col0 + r) * K + k0 + sk;
            *(uint4*)&Bs_h[r * SA + sk] = *(const uint4*)(BhiT + off);
            *(uint4*)&Bs_l[r * SA + sk] = *(const uint4*)(BloT + off);
        }
        __syncthreads();

        #pragma unroll
        for (int ks = 0; ks < 32; ks += 16) {
            uint32_t kb = ks * 2;
            uint32_t ah[2][4], al[2][4], bh[4][2], bl[4][2];
            #pragma unroll
            for (int mt = 0; mt < 2; mt++) {
                LDSM_X4(ah[mt][0], ah[mt][1], ah[mt][2], ah[mt][3], aadH[mt] + kb);
                LDSM_X4(al[mt][0], al[mt][1], al[mt][2], al[mt][3], aadL[mt] + kb);
            }
            #pragma unroll
            for (int nt = 0; nt < 4; nt++) {
                LDSM_X2(bh[nt][0], bh[nt][1], badH[nt] + kb);
                LDSM_X2(bl[nt][0], bl[nt][1], badL[nt] + kb);
            }
            #pragma unroll
            for (int mt = 0; mt < 2; mt++)
                #pragma unroll
                for (int nt = 0; nt < 4; nt++) {
                    mma_bf16(acc[mt][nt], ah[mt][0], ah[mt][1], ah[mt][2], ah[mt][3],
                             bl[nt][0], bl[nt][1]);
                    mma_bf16(acc[mt][nt], al[mt][0], al[mt][1], al[mt][2], al[mt][3],
                             bh[nt][0], bh[nt][1]);
                    mma_bf16(acc[mt][nt], ah[mt][0], ah[mt][1], ah[mt][2], ah[mt][3],
                             bh[nt][0], bh[nt][1]);
                }
        }
        __syncthreads();
    }

    int g = lane >> 2, tg = lane & 3;
    #pragma unroll
    for (int nt = 0; nt < 4; nt++) {
        int col = col0 + warpN * 32 + nt * 8 + 2 * tg;
        float2 bv = *(const float2*)(bias + col);
        #pragma unroll
        for (int mt = 0; mt < 2; mt++) {
            int r = row0 + warpM * 32 + mt * 16 + g;
            if (r < M) {
                float2 v = make_float2(acc[mt][nt][0] + bv.x, acc[mt][nt][1] + bv.y);
                *(float2*)(C + (size_t)r * Ncols + col) = v;
            }
            if (r + 8 < M) {
                float2 v = make_float2(acc[mt][nt][2] + bv.x, acc[mt][nt][3] + bv.y);
                *(float2*)(C + (size_t)(r + 8) * Ncols + col) = v;
            }
        }
    }
}

// ---------------- fused edge aggregation ----------------
// one warp per (node, head), lane owns 2 contiguous channels.
// No max-subtraction (logits O(1)); 4-edge unroll with paired accumulators (R8 config).
template <int H, bool OUT_BF16>
__global__ void edge_agg(const int* __restrict__ rowptr, const int* __restrict__ csr_src,
                         const float4* __restrict__ csr_ea,
                         const float* __restrict__ xl, const float* __restrict__ xr,
                         const float* __restrict__ We, const float* __restrict__ att,
                         const float* __restrict__ bias, float* __restrict__ out_f32,
                         __nv_bfloat16* __restrict__ out_hi, __nv_bfloat16* __restrict__ out_lo) {
    const int D = H * 64;
    int w = (blockIdx.x * blockDim.x + threadIdx.x) >> 5;
    int lane = threadIdx.x & 31;
    int n = w / H;
    int h = w - n * H;
    if (n >= N_NODES) return;

    int c = h * 64 + 2 * lane;
    float2 xrv = *(const float2*)(xr + (size_t)n * D + c);
    float2 atv = *(const float2*)(att + c);
    float2 wev[4];
    #pragma unroll
    for (int f = 0; f < 4; f++) wev[f] = *(const float2*)(We + f * D + c);

    float s0 = 0.f, a00 = 0.f, a01 = 0.f;
    float s1 = 0.f, a10 = 0.f, a11 = 0.f;
    int beg = rowptr[n], end = rowptr[n + 1];

    int i = beg;
    for (; i + 3 < end; i += 4) {
        int sn0 = csr_src[i], sn1 = csr_src[i + 1], sn2 = csr_src[i + 2], sn3 = csr_src[i + 3];
        float4 e0 = csr_ea[i], e1 = csr_ea[i + 1], e2 = csr_ea[i + 2], e3 = csr_ea[i + 3];
        float2 x0 = *(const float2*)(xl + (size_t)sn0 * D + c);
        float2 x1 = *(const float2*)(xl + (size_t)sn1 * D + c);
        float2 x2 = *(const float2*)(xl + (size_t)sn2 * D + c);
        float2 x3 = *(const float2*)(xl + (size_t)sn3 * D + c);

        float za, zb, t0, t1, t2, t3;
        za = x0.x + xrv.x + e0.x * wev[0].x + e0.y * wev[1].x + e0.z * wev[2].x + e0.w * wev[3].x;
        zb = x0.y + xrv.y + e0.x * wev[0].y + e0.y * wev[1].y + e0.z * wev[2].y + e0.w * wev[3].y;
        za = za > 0.f ? za : 0.2f * za; zb = zb > 0.f ? zb : 0.2f * zb;
        t0 = za * atv.x + zb * atv.y;
        za = x1.x + xrv.x + e1.x * wev[0].x + e1.y * wev[1].x + e1.z * wev[2].x + e1.w * wev[3].x;
        zb = x1.y + xrv.y + e1.x * wev[0].y + e1.y * wev[1].y + e1.z * wev[2].y + e1.w * wev[3].y;
        za = za > 0.f ? za : 0.2f * za; zb = zb > 0.f ? zb : 0.2f * zb;
        t1 = za * atv.x + zb * atv.y;
        za = x2.x + xrv.x + e2.x * wev[0].x + e2.y * wev[1].x + e2.z * wev[2].x + e2.w * wev[3].x;
        zb = x2.y + xrv.y + e2.x * wev[0].y + e2.y * wev[1].y + e2.z * wev[2].y + e2.w * wev[3].y;
        za = za > 0.f ? za : 0.2f * za; zb = zb > 0.f ? zb : 0.2f * zb;
        t2 = za * atv.x + zb * atv.y;
        za = x3.x + xrv.x + e3.x * wev[0].x + e3.y * wev[1].x + e3.z * wev[2].x + e3.w * wev[3].x;
        zb = x3.y + xrv.y + e3.x * wev[0].y + e3.y * wev[1].y + e3.z * wev[2].y + e3.w * wev[3].y;
        za = za > 0.f ? za : 0.2f * za; zb = zb > 0.f ? zb : 0.2f * zb;
        t3 = za * atv.x + zb * atv.y;

        #pragma unroll
        for (int o = 16; o > 0; o >>= 1) {
            t0 += __shfl_xor_sync(0xFFFFFFFFu, t0, o);
            t1 += __shfl_xor_sync(0xFFFFFFFFu, t1, o);
            t2 += __shfl_xor_sync(0xFFFFFFFFu, t2, o);
            t3 += __shfl_xor_sync(0xFFFFFFFFu, t3, o);
        }
        float p0 = __expf(t0), p1 = __expf(t1), p2 = __expf(t2), p3 = __expf(t3);
        s0 += p0; a00 += p0 * x0.x; a01 += p0 * x0.y;
        s1 += p1; a10 += p1 * x1.x; a11 += p1 * x1.y;
        s0 += p2; a00 += p2 * x2.x; a01 += p2 * x2.y;
        s1 += p3; a10 += p3 * x3.x; a11 += p3 * x3.y;
    }
    for (; i < end; i++) {
        int sn = csr_src[i];
        float4 eav = csr_ea[i];
        float2 xv = *(const float2*)(xl + (size_t)sn * D + c);
        float z0 = xv.x + xrv.x + eav.x * wev[0].x + eav.y * wev[1].x + eav.z * wev[2].x + eav.w * wev[3].x;
        float z1 = xv.y + xrv.y + eav.x * wev[0].y + eav.y * wev[1].y + eav.z * wev[2].y + eav.w * wev[3].y;
        z0 = z0 > 0.f ? z0 : 0.2f * z0;
        z1 = z1 > 0.f ? z1 : 0.2f * z1;
        float t = z0 * atv.x + z1 * atv.y;
        #pragma unroll
        for (int o = 16; o > 0; o >>= 1) t += __shfl_xor_sync(0xFFFFFFFFu, t, o);
        float p = __expf(t);
        s0 += p; a00 += p * xv.x; a01 += p * xv.y;
    }
    float s = s0 + s1;
    float a0 = a00 + a10;
    float a1 = a01 + a11;

    float inv = 1.f / (s + 1e-16f);
    float2 bv = *(const float2*)(bias + c);
    float r0 = a0 * inv + bv.x;
    float r1 = a1 * inv + bv.y;
    if (OUT_BF16) {
        r0 = r0 > 0.f ? r0 : expm1f(r0);
        r1 = r1 > 0.f ? r1 : expm1f(r1);
        __nv_bfloat16 h0 = __float2bfloat16(r0);
        __nv_bfloat16 h1 = __float2bfloat16(r1);
        __nv_bfloat16 l0 = __float2bfloat16(r0 - __bfloat162float(h0));
        __nv_bfloat16 l1 = __float2bfloat16(r1 - __bfloat162float(h1));
        __nv_bfloat162 hv; hv.x = h0; hv.y = h1;
        __nv_bfloat162 lv; lv.x = l0; lv.y = l1;
        *(__nv_bfloat162*)(out_hi + (size_t)n * D + c) = hv;
        *(__nv_bfloat162*)(out_lo + (size_t)n * D + c) = lv;
    } else {
        *(float2*)(out_f32 + (size_t)n * D + c) = make_float2(r0, r1);
    }
}

// ---------------- global mean pool ----------------
__global__ void pool_k(const float* __restrict__ h, const int* __restrict__ batch,
                       float* __restrict__ sums, int* __restrict__ cnt) {
    int idx = blockIdx.x * blockDim.x + threadIdx.x;
    if (idx >= N_NODES * 64) return;
    int n = idx >> 6;
    int ch = idx & 63;
    int g = batch[n];
    atomicAdd(&sums[g * 64 + ch], h[idx]);
    if (ch == 0) atomicAdd(&cnt[g], 1);
}

// ---------------- MLP head ----------------
__global__ void mlp_k(const float* __restrict__ sums, const int* __restrict__ cnt,
                      const float* __restrict__ mW1, const float* __restrict__ mb1,
                      const float* __restrict__ mW2, const float* __restrict__ mb2,
                      const float* __restrict__ mW3, const float* __restrict__ mb3,
                      float* __restrict__ out) {
    __shared__ float gv[64];
    __shared__ float h1[32];
    __shared__ float h2[16];
    int g = blockIdx.x, t = threadIdx.x;
    float cf = fmaxf((float)cnt[g], 1.f);
    gv[t] = sums[g * 64 + t] / cf;
    __syncthreads();
    if (t < 32) {
        float a = mb1[t];
        #pragma unroll
        for (int k = 0; k < 64; k++) a += gv[k] * mW1[k * 32 + t];
        h1[t] = fmaxf(a, 0.f);
    }
    __syncthreads();
    if (t < 16) {
        float a = mb2[t];
        #pragma unroll
        for (int k = 0; k < 32; k++) a += h1[k] * mW2[k * 16 + t];
        h2[t] = fmaxf(a, 0.f);
    }
    __syncthreads();
    if (t < 4) {
        float a = mb3[t];
        #pragma unroll
        for (int k = 0; k < 16; k++) a += h2[k] * mW3[k * 4 + t];
        out[g * 4 + t] = a;
    }
}

// ---------------- launch ----------------
extern "C" void kernel_launch(void* const* d_in, const int* in_sizes, int n_in,
                              void* d_out, int out_size) {
    (void)in_sizes; (void)n_in; (void)out_size;
    const float* x     = (const float*)d_in[0];
    const int*   ei    = (const int*)d_in[1];
    const float* ea    = (const float*)d_in[2];
    const int*   batch = (const int*)d_in[3];
    const float* Wl1 = (const float*)d_in[4],  *bl1 = (const float*)d_in[5];
    const float* Wr1 = (const float*)d_in[6],  *br1 = (const float*)d_in[7];
    const float* We1 = (const float*)d_in[8],  *att1 = (const float*)d_in[9],  *bias1 = (const float*)d_in[10];
    const float* Wl2 = (const float*)d_in[11], *bl2 = (const float*)d_in[12];
    const float* Wr2 = (const float*)d_in[13], *br2 = (const float*)d_in[14];
    const float* We2 = (const float*)d_in[15], *att2 = (const float*)d_in[16], *bias2 = (const float*)d_in[17];
    const float* Wl3 = (const float*)d_in[18], *bl3 = (const float*)d_in[19];
    const float* Wr3 = (const float*)d_in[20], *br3 = (const float*)d_in[21];
    const float* We3 = (const float*)d_in[22], *att3 = (const float*)d_in[23], *bias3 = (const float*)d_in[24];
    const float* mW1 = (const float*)d_in[25], *mb1 = (const float*)d_in[26];
    const float* mW2 = (const float*)d_in[27], *mb2 = (const float*)d_in[28];
    const float* mW3 = (const float*)d_in[29], *mb3 = (const float*)d_in[30];
    float* out = (float*)d_out;

    const int* srcp = ei;
    const int* dstp = ei + N_EDGES;

    float *xl, *xr, *hA, *sums;
    int *deg, *rowptr, *cursor, *csr_src, *cnt;
    float4* csr_ea;
    __nv_bfloat16 *ahi, *alo, *whL, *wlL, *whR, *wlR;
    cudaGetSymbolAddress((void**)&xl, g_xl);
    cudaGetSymbolAddress((void**)&xr, g_xr);
    cudaGetSymbolAddress((void**)&hA, g_hA);
    cudaGetSymbolAddress((void**)&sums, g_sums);
    cudaGetSymbolAddress((void**)&deg, g_deg);
    cudaGetSymbolAddress((void**)&rowptr, g_rowptr);
    cudaGetSymbolAddress((void**)&cursor, g_cursor);
    cudaGetSymbolAddress((void**)&csr_src, g_csr_src);
    cudaGetSymbolAddress((void**)&csr_ea, g_csr_ea);
    cudaGetSymbolAddress((void**)&cnt, g_cnt);
    cudaGetSymbolAddress((void**)&ahi, g_ahi);
    cudaGetSymbolAddress((void**)&alo, g_alo);
    cudaGetSymbolAddress((void**)&whL, g_whL);
    cudaGetSymbolAddress((void**)&wlL, g_wlL);
    cudaGetSymbolAddress((void**)&whR, g_whR);
    cudaGetSymbolAddress((void**)&wlR, g_wlR);

    // launches 1-4: CSR by destination (shared by all 3 layers)
    zero_i32<<<(N_NODES + 255) / 256, 256>>>(deg, N_NODES);
    hist_k<<<(N_EDGES + 255) / 256, 256>>>(dstp, deg);
    scan_k<<<1, 1024>>>(deg, rowptr, cursor);
    scatter_k<<<(N_EDGES + 255) / 256, 256>>>(srcp, dstp, (const float4*)ea, cursor, csr_src, csr_ea);

    // launch 5: layer-1 dual GEMM (xl + xr in one pass)
    gemm_k12_dual<<<(N_NODES + 31) / 32, 256>>>(x, Wl1, bl1, Wr1, br1, xl, xr);

    // launch 6: edge_agg<4> — profiled by ncu (-s 5 -c 1)
    edge_agg<4, true><<<10000, 256>>>(rowptr, csr_src, csr_ea, xl, xr, We1, att1, bias1,
                                      nullptr, ahi, alo);

    // ---- layer 2 (256 -> 256, H=4) ----
    splitW_dual<<<(256 * 256 + 255) / 256, 256>>>(Wl2, Wr2, whL, wlL, whR, wlR, 256, 256);
    gemm_bf16<<<dim3(4, 157), 256>>>(ahi, alo, whL, wlL, bl2, xl, N_NODES, 256, 256);
    gemm_bf16<<<dim3(4, 157), 256>>>(ahi, alo, whR, wlR, br2, xr, N_NODES, 256, 256);
    edge_agg<4, true><<<10000, 256>>>(rowptr, csr_src, csr_ea, xl, xr, We2, att2, bias2,
                                      nullptr, ahi, alo);

    // ---- layer 3 (256 -> 64, H=1, no ELU) ----
    splitW_dual<<<(256 * 64 + 255) / 256, 256>>>(Wl3, Wr3, whL, wlL, whR, wlR, 256, 64);
    gemm_bf16<<<dim3(1, 157), 256>>>(ahi, alo, whL, wlL, bl3, xl, N_NODES, 256, 64);
    gemm_bf16<<<dim3(1, 157), 256>>>(ahi, alo, whR, wlR, br3, xr, N_NODES, 256, 64);
    edge_agg<1, false><<<2500, 256>>>(rowptr, csr_src, csr_ea, xl, xr, We3, att3, bias3,
                                      hA, nullptr, nullptr);

    // ---- global mean pool + MLP head ----
    zero_f32<<<(N_GRAPHS * 64 + 255) / 256, 256>>>(sums, N_GRAPHS * 64);
    zero_i32<<<(N_GRAPHS + 255) / 256, 256>>>(cnt, N_GRAPHS);
    pool_k<<<(N_NODES * 64 + 255) / 256, 256>>>(hA, batch, sums, cnt);
    mlp_k<<<N_GRAPHS, 64>>>(sums, cnt, mW1, mb1, mW2, mb2, mW3, mb3, out);
}

// round 11
// speedup vs baseline: 1.1847x; 1.0589x over previous
#include <cuda_runtime.h>
#include <cuda_bf16.h>
#include <math.h>
#include <stdint.h>

#define N_NODES  20000
#define N_EDGES  320000
#define N_GRAPHS 1000

// ---------------- static device scratch (no allocations allowed) ----------------
__device__ float    g_xl[N_NODES * 256];
__device__ float    g_xr[N_NODES * 256];
__device__ float    g_hA[N_NODES * 256];
__device__ uint16_t g_ahi[N_NODES * 256];
__device__ uint16_t g_alo[N_NODES * 256];
__device__ uint16_t g_whL[256 * 256];
__device__ uint16_t g_wlL[256 * 256];
__device__ uint16_t g_whR[256 * 256];
__device__ uint16_t g_wlR[256 * 256];
__device__ int      g_deg[N_NODES];
__device__ int      g_rowptr[N_NODES + 1];
__device__ int      g_cursor[N_NODES];
__device__ int      g_csr_src[N_EDGES];
__device__ float4   g_csr_ea[N_EDGES];
__device__ float    g_sums[N_GRAPHS * 64];
__device__ int      g_cnt[N_GRAPHS];

// ---------------- utility kernels ----------------
__global__ void zero_i32(int* p, int n) {
    int i = blockIdx.x * blockDim.x + threadIdx.x;
    if (i < n) p[i] = 0;
}
__global__ void zero_f32(float* p, int n) {
    int i = blockIdx.x * blockDim.x + threadIdx.x;
    if (i < n) p[i] = 0.f;
}
__global__ void hist_k(const int* __restrict__ dst, int* __restrict__ deg) {
    int e = blockIdx.x * blockDim.x + threadIdx.x;
    if (e < N_EDGES) atomicAdd(&deg[dst[e]], 1);
}

__global__ void scan_k(const int* __restrict__ deg, int* __restrict__ rowptr,
                       int* __restrict__ cursor) {
    __shared__ int sh[1024];
    const int CH = 20;
    int t = threadIdx.x;
    int base = t * CH;
    int loc[CH];
    int s = 0;
    #pragma unroll
    for (int i = 0; i < CH; i++) {
        int idx = base + i;
        int v = (idx < N_NODES) ? deg[idx] : 0;
        loc[i] = s;
        s += v;
    }
    sh[t] = s;
    __syncthreads();
    for (int off = 1; off < 1024; off <<= 1) {
        int v = (t >= off) ? sh[t - off] : 0;
        __syncthreads();
        sh[t] += v;
        __syncthreads();
    }
    int pre = (t > 0) ? sh[t - 1] : 0;
    #pragma unroll
    for (int i = 0; i < CH; i++) {
        int idx = base + i;
        if (idx < N_NODES) {
            int v = pre + loc[i];
            rowptr[idx] = v;
            cursor[idx] = v;
        }
    }
    if (t == 1023) rowptr[N_NODES] = sh[1023];
}

__global__ void scatter_k(const int* __restrict__ src, const int* __restrict__ dst,
                          const float4* __restrict__ ea, int* __restrict__ cursor,
                          int* __restrict__ csr_src, float4* __restrict__ csr_ea) {
    int e = blockIdx.x * blockDim.x + threadIdx.x;
    if (e < N_EDGES) {
        int p = atomicAdd(&cursor[dst[e]], 1);
        csr_src[p] = src[e];
        csr_ea[p] = ea[e];
    }
}

// dual W split: both L and R weights, W[K][Nc] fp32 -> transposed [Nc][K] bf16 hi/lo
__global__ void splitW_dual(const float* __restrict__ WL, const float* __restrict__ WR,
                            __nv_bfloat16* __restrict__ hiL, __nv_bfloat16* __restrict__ loL,
                            __nv_bfloat16* __restrict__ hiR, __nv_bfloat16* __restrict__ loR,
                            int K, int Nc) {
    int i = blockIdx.x * blockDim.x + threadIdx.x;
    if (i < K * Nc) {
        int k = i / Nc, n = i - k * Nc;
        float v = WL[i];
        __nv_bfloat16 h = __float2bfloat16(v);
        hiL[(size_t)n * K + k] = h;
        loL[(size_t)n * K + k] = __float2bfloat16(v - __bfloat162float(h));
        v = WR[i];
        h = __float2bfloat16(v);
        hiR[(size_t)n * K + k] = h;
        loR[(size_t)n * K + k] = __float2bfloat16(v - __bfloat162float(h));
    }
}

// ---------------- layer-1 dual GEMM (K=12 -> 256 for both Wl and Wr) ----------------
__global__ void gemm_k12_dual(const float* __restrict__ x,
                              const float* __restrict__ WL, const float* __restrict__ bL,
                              const float* __restrict__ WR, const float* __restrict__ bR,
                              float* __restrict__ xl, float* __restrict__ xr) {
    __shared__ float WsL[12 * 256];
    __shared__ float WsR[12 * 256];
    __shared__ float xs[32 * 12];
    int tid = threadIdx.x;
    int r0 = blockIdx.x * 32;
    for (int i = tid; i < 12 * 256; i += 256) {
        WsL[i] = WL[i];
        WsR[i] = WR[i];
    }
    for (int i = tid; i < 32 * 12; i += 256) {
        int r = r0 + i / 12;
        xs[i] = (r < N_NODES) ? x[(size_t)r * 12 + (i % 12)] : 0.f;
    }
    __syncthreads();
    float bbL = bL[tid], bbR = bR[tid];
    for (int r = 0; r < 32; r++) {
        int gr = r0 + r;
        if (gr >= N_NODES) break;
        float accL = bbL, accR = bbR;
        #pragma unroll
        for (int k = 0; k < 12; k++) {
            float xv = xs[r * 12 + k];
            accL += xv * WsL[k * 256 + tid];
            accR += xv * WsR[k * 256 + tid];
        }
        xl[(size_t)gr * 256 + tid] = accL;
        xr[(size_t)gr * 256 + tid] = accR;
    }
}

// ---------------- bf16 mma.sync GEMM with pre-split hi/lo (3-term) ----------------
__device__ __forceinline__ uint32_t smem_u32(const void* p) {
    uint32_t a;
    asm("{ .reg .u64 t; cvta.to.shared.u64 t, %1; cvt.u32.u64 %0, t; }" : "=r"(a) : "l"(p));
    return a;
}
#define LDSM_X4(r0, r1, r2, r3, addr) \
    asm volatile("ldmatrix.sync.aligned.m8n8.x4.shared.b16 {%0,%1,%2,%3}, [%4];" \
                 : "=r"(r0), "=r"(r1), "=r"(r2), "=r"(r3) : "r"(addr))
#define LDSM_X2(r0, r1, addr) \
    asm volatile("ldmatrix.sync.aligned.m8n8.x2.shared.b16 {%0,%1}, [%2];" \
                 : "=r"(r0), "=r"(r1) : "r"(addr))
__device__ __forceinline__ void mma_bf16(float* d, uint32_t a0, uint32_t a1,
                                         uint32_t a2, uint32_t a3,
                                         uint32_t b0, uint32_t b1) {
    asm volatile(
        "mma.sync.aligned.m16n8k16.row.col.f32.bf16.bf16.f32 "
        "{%0,%1,%2,%3},{%4,%5,%6,%7},{%8,%9},{%0,%1,%2,%3};"
        : "+f"(d[0]), "+f"(d[1]), "+f"(d[2]), "+f"(d[3])
        : "r"(a0), "r"(a1), "r"(a2), "r"(a3), "r"(b0), "r"(b1));
}

// C[M,Ncols] = A @ W + bias. BM=128, BN=64, BK=32. 256 threads = 8 warps.
__global__ __launch_bounds__(256) void gemm_bf16(
    const __nv_bfloat16* __restrict__ Ahi, const __nv_bfloat16* __restrict__ Alo,
    const __nv_bfloat16* __restrict__ BhiT, const __nv_bfloat16* __restrict__ BloT,
    const float* __restrict__ bias, float* __restrict__ C, int M, int K, int Ncols) {
    const int SA = 40;
    __shared__ __align__(16) uint16_t As_h[128 * 40];
    __shared__ __align__(16) uint16_t As_l[128 * 40];
    __shared__ __align__(16) uint16_t Bs_h[64 * 40];
    __shared__ __align__(16) uint16_t Bs_l[64 * 40];

    int tid = threadIdx.x, lane = tid & 31, warp = tid >> 5;
    int warpM = warp & 3, warpN = warp >> 2;
    int row0 = blockIdx.y * 128, col0 = blockIdx.x * 64;

    float acc[2][4][4];
    #pragma unroll
    for (int mt = 0; mt < 2; mt++)
        #pragma unroll
        for (int nt = 0; nt < 4; nt++)
            #pragma unroll
            for (int i = 0; i < 4; i++) acc[mt][nt][i] = 0.f;

    uint32_t aadH[2], aadL[2], badH[4], badL[4];
    {
        int ar = (lane & 7) + ((lane >> 3) & 1) * 8;
        int ac = (lane >> 4) * 8;
        #pragma unroll
        for (int mt = 0; mt < 2; mt++) {
            int r = warpM * 32 + mt * 16 + ar;
            aadH[mt] = smem_u32(As_h) + (uint32_t)(r * SA + ac) * 2;
            aadL[mt] = smem_u32(As_l) + (uint32_t)(r * SA + ac) * 2;
        }
        int l16 = lane & 15;
        int bn = l16 & 7;
        int bc = ((l16 >> 3) & 1) * 8;
        #pragma unroll
        for (int nt = 0; nt < 4; nt++) {
            int n = warpN * 32 + nt * 8 + bn;
            badH[nt] = smem_u32(Bs_h) + (uint32_t)(n * SA + bc) * 2;
            badL[nt] = smem_u32(Bs_l) + (uint32_t)(n * SA + bc) * 2;
        }
    }

    for (int k0 = 0; k0 < K; k0 += 32) {
        #pragma unroll
        for (int it = 0; it < 2; it++) {
            int idx = tid + it * 256;
            int r = idx >> 2, sk = (idx & 3) * 8;
            int grow = row0 + r;
            uint4 vh = make_uint4(0, 0, 0, 0), vl = make_uint4(0, 0, 0, 0);
            if (grow < M) {
                size_t off = (size_t)grow * K + k0 + sk;
                vh = *(const uint4*)(Ahi + off);
                vl = *(const uint4*)(Alo + off);
            }
            *(uint4*)&As_h[r * SA + sk] = vh;
            *(uint4*)&As_l[r * SA + sk] = vl;
        }
        {
            int r = tid >> 2, sk = (tid & 3) * 8;
            size_t off = (size_t)(col0 + r) * K + k0 + sk;
            *(uint4*)&Bs_h[r * SA + sk] = *(const uint4*)(BhiT + off);
            *(uint4*)&Bs_l[r * SA + sk] = *(const uint4*)(BloT + off);
        }
        __syncthreads();

        #pragma unroll
        for (int ks = 0; ks < 32; ks += 16) {
            uint32_t kb = ks * 2;
            uint32_t ah[2][4], al[2][4], bh[4][2], bl[4][2];
            #pragma unroll
            for (int mt = 0; mt < 2; mt++) {
                LDSM_X4(ah[mt][0], ah[mt][1], ah[mt][2], ah[mt][3], aadH[mt] + kb);
                LDSM_X4(al[mt][0], al[mt][1], al[mt][2], al[mt][3], aadL[mt] + kb);
            }
            #pragma unroll
            for (int nt = 0; nt < 4; nt++) {
                LDSM_X2(bh[nt][0], bh[nt][1], badH[nt] + kb);
                LDSM_X2(bl[nt][0], bl[nt][1], badL[nt] + kb);
            }
            #pragma unroll
            for (int mt = 0; mt < 2; mt++)
                #pragma unroll
                for (int nt = 0; nt < 4; nt++) {
                    mma_bf16(acc[mt][nt], ah[mt][0], ah[mt][1], ah[mt][2], ah[mt][3],
                             bl[nt][0], bl[nt][1]);
                    mma_bf16(acc[mt][nt], al[mt][0], al[mt][1], al[mt][2], al[mt][3],
                             bh[nt][0], bh[nt][1]);
                    mma_bf16(acc[mt][nt], ah[mt][0], ah[mt][1], ah[mt][2], ah[mt][3],
                             bh[nt][0], bh[nt][1]);
                }
        }
        __syncthreads();
    }

    int g = lane >> 2, tg = lane & 3;
    #pragma unroll
    for (int nt = 0; nt < 4; nt++) {
        int col = col0 + warpN * 32 + nt * 8 + 2 * tg;
        float2 bv = *(const float2*)(bias + col);
        #pragma unroll
        for (int mt = 0; mt < 2; mt++) {
            int r = row0 + warpM * 32 + mt * 16 + g;
            if (r < M) {
                float2 v = make_float2(acc[mt][nt][0] + bv.x, acc[mt][nt][1] + bv.y);
                *(float2*)(C + (size_t)r * Ncols + col) = v;
            }
            if (r + 8 < M) {
                float2 v = make_float2(acc[mt][nt][2] + bv.x, acc[mt][nt][3] + bv.y);
                *(float2*)(C + (size_t)(r + 8) * Ncols + col) = v;
            }
        }
    }
}

// ---------------- fused edge aggregation, H=4: ONE warp per node (all heads) -------
// lane owns 8 contiguous channels (c = lane*8); head h = lane group [8h, 8h+8).
// Per-edge: 2x LDG.128 xl, 1x CSR src + ea (no 4x redundancy), in-lane 8-FMA logit
// partial + 3-SHFL group butterfly (per-head logits converge per 8-lane group).
// No max-subtraction (logits O(1)). 2-edge unroll. Writes bf16 hi/lo after ELU.
__global__ void edge_agg_h4(const int* __restrict__ rowptr, const int* __restrict__ csr_src,
                            const float4* __restrict__ csr_ea,
                            const float* __restrict__ xl, const float* __restrict__ xr,
                            const float* __restrict__ We, const float* __restrict__ att,
                            const float* __restrict__ bias,
                            __nv_bfloat16* __restrict__ out_hi,
                            __nv_bfloat16* __restrict__ out_lo) {
    int w = (blockIdx.x * blockDim.x + threadIdx.x) >> 5;  // node
    int lane = threadIdx.x & 31;
    if (w >= N_NODES) return;
    int n = w;
    int c = lane * 8;

    float xrv[8], atv[8], wev[4][8];
    {
        float4 v0 = *(const float4*)(xr + (size_t)n * 256 + c);
        float4 v1 = *(const float4*)(xr + (size_t)n * 256 + c + 4);
        xrv[0] = v0.x; xrv[1] = v0.y; xrv[2] = v0.z; xrv[3] = v0.w;
        xrv[4] = v1.x; xrv[5] = v1.y; xrv[6] = v1.z; xrv[7] = v1.w;
        v0 = *(const float4*)(att + c);
        v1 = *(const float4*)(att + c + 4);
        atv[0] = v0.x; atv[1] = v0.y; atv[2] = v0.z; atv[3] = v0.w;
        atv[4] = v1.x; atv[5] = v1.y; atv[6] = v1.z; atv[7] = v1.w;
        #pragma unroll
        for (int f = 0; f < 4; f++) {
            v0 = *(const float4*)(We + f * 256 + c);
            v1 = *(const float4*)(We + f * 256 + c + 4);
            wev[f][0] = v0.x; wev[f][1] = v0.y; wev[f][2] = v0.z; wev[f][3] = v0.w;
            wev[f][4] = v1.x; wev[f][5] = v1.y; wev[f][6] = v1.z; wev[f][7] = v1.w;
        }
    }

    float s = 0.f, a[8];
    #pragma unroll
    for (int j = 0; j < 8; j++) a[j] = 0.f;
    int beg = rowptr[n], end = rowptr[n + 1];

    int i = beg;
    for (; i + 1 < end; i += 2) {
        int sn0 = csr_src[i], sn1 = csr_src[i + 1];
        float4 e0 = csr_ea[i], e1 = csr_ea[i + 1];
        float4 xa0 = *(const float4*)(xl + (size_t)sn0 * 256 + c);
        float4 xb0 = *(const float4*)(xl + (size_t)sn0 * 256 + c + 4);
        float4 xa1 = *(const float4*)(xl + (size_t)sn1 * 256 + c);
        float4 xb1 = *(const float4*)(xl + (size_t)sn1 * 256 + c + 4);
        float x0[8] = {xa0.x, xa0.y, xa0.z, xa0.w, xb0.x, xb0.y, xb0.z, xb0.w};
        float x1[8] = {xa1.x, xa1.y, xa1.z, xa1.w, xb1.x, xb1.y, xb1.z, xb1.w};

        float t0 = 0.f, t1 = 0.f;
        #pragma unroll
        for (int j = 0; j < 8; j++) {
            float z0 = x0[j] + xrv[j] + e0.x * wev[0][j] + e0.y * wev[1][j]
                       + e0.z * wev[2][j] + e0.w * wev[3][j];
            float z1 = x1[j] + xrv[j] + e1.x * wev[0][j] + e1.y * wev[1][j]
                       + e1.z * wev[2][j] + e1.w * wev[3][j];
            z0 = z0 > 0.f ? z0 : 0.2f * z0;
            z1 = z1 > 0.f ? z1 : 0.2f * z1;
            t0 += z0 * atv[j];
            t1 += z1 * atv[j];
        }
        #pragma unroll
        for (int o = 4; o > 0; o >>= 1) {
            t0 += __shfl_xor_sync(0xFFFFFFFFu, t0, o);
            t1 += __shfl_xor_sync(0xFFFFFFFFu, t1, o);
        }
        float p0 = __expf(t0), p1 = __expf(t1);
        s += p0 + p1;
        #pragma unroll
        for (int j = 0; j < 8; j++) a[j] += p0 * x0[j] + p1 * x1[j];
    }
    if (i < end) {
        int sn = csr_src[i];
        float4 eav = csr_ea[i];
        float4 xa = *(const float4*)(xl + (size_t)sn * 256 + c);
        float4 xb = *(const float4*)(xl + (size_t)sn * 256 + c + 4);
        float xv[8] = {xa.x, xa.y, xa.z, xa.w, xb.x, xb.y, xb.z, xb.w};
        float t = 0.f;
        #pragma unroll
        for (int j = 0; j < 8; j++) {
            float z = xv[j] + xrv[j] + eav.x * wev[0][j] + eav.y * wev[1][j]
                      + eav.z * wev[2][j] + eav.w * wev[3][j];
            z = z > 0.f ? z : 0.2f * z;
            t += z * atv[j];
        }
        #pragma unroll
        for (int o = 4; o > 0; o >>= 1) t += __shfl_xor_sync(0xFFFFFFFFu, t, o);
        float p = __expf(t);
        s += p;
        #pragma unroll
        for (int j = 0; j < 8; j++) a[j] += p * xv[j];
    }

    float inv = 1.f / (s + 1e-16f);
    float4 bv0 = *(const float4*)(bias + c);
    float4 bv1 = *(const float4*)(bias + c + 4);
    float bb[8] = {bv0.x, bv0.y, bv0.z, bv0.w, bv1.x, bv1.y, bv1.z, bv1.w};
    uint16_t hv[8], lv[8];
    #pragma unroll
    for (int j = 0; j < 8; j++) {
        float r = a[j] * inv + bb[j];
        r = r > 0.f ? r : expm1f(r);   // ELU
        __nv_bfloat16 h = __float2bfloat16(r);
        __nv_bfloat16 l = __float2bfloat16(r - __bfloat162float(h));
        hv[j] = *(uint16_t*)&h;
        lv[j] = *(uint16_t*)&l;
    }
    *(uint4*)(out_hi + (size_t)n * 256 + c) = *(uint4*)hv;
    *(uint4*)(out_lo + (size_t)n * 256 + c) = *(uint4*)lv;
}

// ---------------- edge aggregation, H=1 (layer 3): R8 config, fp32 out, no ELU -----
__global__ void edge_agg_h1(const int* __restrict__ rowptr, const int* __restrict__ csr_src,
                            const float4* __restrict__ csr_ea,
                            const float* __restrict__ xl, const float* __restrict__ xr,
                            const float* __restrict__ We, const float* __restrict__ att,
                            const float* __restrict__ bias, float* __restrict__ out_f32) {
    const int D = 64;
    int w = (blockIdx.x * blockDim.x + threadIdx.x) >> 5;
    int lane = threadIdx.x & 31;
    int n = w;
    if (n >= N_NODES) return;

    int c = 2 * lane;
    float2 xrv = *(const float2*)(xr + (size_t)n * D + c);
    float2 atv = *(const float2*)(att + c);
    float2 wev[4];
    #pragma unroll
    for (int f = 0; f < 4; f++) wev[f] = *(const float2*)(We + f * D + c);

    float s0 = 0.f, a00 = 0.f, a01 = 0.f;
    float s1 = 0.f, a10 = 0.f, a11 = 0.f;
    int beg = rowptr[n], end = rowptr[n + 1];

    int i = beg;
    for (; i + 3 < end; i += 4) {
        int sn0 = csr_src[i], sn1 = csr_src[i + 1], sn2 = csr_src[i + 2], sn3 = csr_src[i + 3];
        float4 e0 = csr_ea[i], e1 = csr_ea[i + 1], e2 = csr_ea[i + 2], e3 = csr_ea[i + 3];
        float2 x0 = *(const float2*)(xl + (size_t)sn0 * D + c);
        float2 x1 = *(const float2*)(xl + (size_t)sn1 * D + c);
        float2 x2 = *(const float2*)(xl + (size_t)sn2 * D + c);
        float2 x3 = *(const float2*)(xl + (size_t)sn3 * D + c);

        float za, zb, t0, t1, t2, t3;
        za = x0.x + xrv.x + e0.x * wev[0].x + e0.y * wev[1].x + e0.z * wev[2].x + e0.w * wev[3].x;
        zb = x0.y + xrv.y + e0.x * wev[0].y + e0.y * wev[1].y + e0.z * wev[2].y + e0.w * wev[3].y;
        za = za > 0.f ? za : 0.2f * za; zb = zb > 0.f ? zb : 0.2f * zb;
        t0 = za * atv.x + zb * atv.y;
        za = x1.x + xrv.x + e1.x * wev[0].x + e1.y * wev[1].x + e1.z * wev[2].x + e1.w * wev[3].x;
        zb = x1.y + xrv.y + e1.x * wev[0].y + e1.y * wev[1].y + e1.z * wev[2].y + e1.w * wev[3].y;
        za = za > 0.f ? za : 0.2f * za; zb = zb > 0.f ? zb : 0.2f * zb;
        t1 = za * atv.x + zb * atv.y;
        za = x2.x + xrv.x + e2.x * wev[0].x + e2.y * wev[1].x + e2.z * wev[2].x + e2.w * wev[3].x;
        zb = x2.y + xrv.y + e2.x * wev[0].y + e2.y * wev[1].y + e2.z * wev[2].y + e2.w * wev[3].y;
        za = za > 0.f ? za : 0.2f * za; zb = zb > 0.f ? zb : 0.2f * zb;
        t2 = za * atv.x + zb * atv.y;
        za = x3.x + xrv.x + e3.x * wev[0].x + e3.y * wev[1].x + e3.z * wev[2].x + e3.w * wev[3].x;
        zb = x3.y + xrv.y + e3.x * wev[0].y + e3.y * wev[1].y + e3.z * wev[2].y + e3.w * wev[3].y;
        za = za > 0.f ? za : 0.2f * za; zb = zb > 0.f ? zb : 0.2f * zb;
        t3 = za * atv.x + zb * atv.y;

        #pragma unroll
        for (int o = 16; o > 0; o >>= 1) {
            t0 += __shfl_xor_sync(0xFFFFFFFFu, t0, o);
            t1 += __shfl_xor_sync(0xFFFFFFFFu, t1, o);
            t2 += __shfl_xor_sync(0xFFFFFFFFu, t2, o);
            t3 += __shfl_xor_sync(0xFFFFFFFFu, t3, o);
        }
        float p0 = __expf(t0), p1 = __expf(t1), p2 = __expf(t2), p3 = __expf(t3);
        s0 += p0; a00 += p0 * x0.x; a01 += p0 * x0.y;
        s1 += p1; a10 += p1 * x1.x; a11 += p1 * x1.y;
        s0 += p2; a00 += p2 * x2.x; a01 += p2 * x2.y;
        s1 += p3; a10 += p3 * x3.x; a11 += p3 * x3.y;
    }
    for (; i < end; i++) {
        int sn = csr_src[i];
        float4 eav = csr_ea[i];
        float2 xv = *(const float2*)(xl + (size_t)sn * D + c);
        float z0 = xv.x + xrv.x + eav.x * wev[0].x + eav.y * wev[1].x + eav.z * wev[2].x + eav.w * wev[3].x;
        float z1 = xv.y + xrv.y + eav.x * wev[0].y + eav.y * wev[1].y + eav.z * wev[2].y + eav.w * wev[3].y;
        z0 = z0 > 0.f ? z0 : 0.2f * z0;
        z1 = z1 > 0.f ? z1 : 0.2f * z1;
        float t = z0 * atv.x + z1 * atv.y;
        #pragma unroll
        for (int o = 16; o > 0; o >>= 1) t += __shfl_xor_sync(0xFFFFFFFFu, t, o);
        float p = __expf(t);
        s0 += p; a00 += p * xv.x; a01 += p * xv.y;
    }
    float s = s0 + s1;
    float a0 = a00 + a10;
    float a1 = a01 + a11;

    float inv = 1.f / (s + 1e-16f);
    float2 bv = *(const float2*)(bias + c);
    *(float2*)(out_f32 + (size_t)n * D + c) = make_float2(a0 * inv + bv.x, a1 * inv + bv.y);
}

// ---------------- global mean pool ----------------
__global__ void pool_k(const float* __restrict__ h, const int* __restrict__ batch,
                       float* __restrict__ sums, int* __restrict__ cnt) {
    int idx = blockIdx.x * blockDim.x + threadIdx.x;
    if (idx >= N_NODES * 64) return;
    int n = idx >> 6;
    int ch = idx & 63;
    int g = batch[n];
    atomicAdd(&sums[g * 64 + ch], h[idx]);
    if (ch == 0) atomicAdd(&cnt[g], 1);
}

// ---------------- MLP head ----------------
__global__ void mlp_k(const float* __restrict__ sums, const int* __restrict__ cnt,
                      const float* __restrict__ mW1, const float* __restrict__ mb1,
                      const float* __restrict__ mW2, const float* __restrict__ mb2,
                      const float* __restrict__ mW3, const float* __restrict__ mb3,
                      float* __restrict__ out) {
    __shared__ float gv[64];
    __shared__ float h1[32];
    __shared__ float h2[16];
    int g = blockIdx.x, t = threadIdx.x;
    float cf = fmaxf((float)cnt[g], 1.f);
    gv[t] = sums[g * 64 + t] / cf;
    __syncthreads();
    if (t < 32) {
        float a = mb1[t];
        #pragma unroll
        for (int k = 0; k < 64; k++) a += gv[k] * mW1[k * 32 + t];
        h1[t] = fmaxf(a, 0.f);
    }
    __syncthreads();
    if (t < 16) {
        float a = mb2[t];
        #pragma unroll
        for (int k = 0; k < 32; k++) a += h1[k] * mW2[k * 16 + t];
        h2[t] = fmaxf(a, 0.f);
    }
    __syncthreads();
    if (t < 4) {
        float a = mb3[t];
        #pragma unroll
        for (int k = 0; k < 16; k++) a += h2[k] * mW3[k * 4 + t];
        out[g * 4 + t] = a;
    }
}

// ---------------- launch ----------------
extern "C" void kernel_launch(void* const* d_in, const int* in_sizes, int n_in,
                              void* d_out, int out_size) {
    (void)in_sizes; (void)n_in; (void)out_size;
    const float* x     = (const float*)d_in[0];
    const int*   ei    = (const int*)d_in[1];
    const float* ea    = (const float*)d_in[2];
    const int*   batch = (const int*)d_in[3];
    const float* Wl1 = (const float*)d_in[4],  *bl1 = (const float*)d_in[5];
    const float* Wr1 = (const float*)d_in[6],  *br1 = (const float*)d_in[7];
    const float* We1 = (const float*)d_in[8],  *att1 = (const float*)d_in[9],  *bias1 = (const float*)d_in[10];
    const float* Wl2 = (const float*)d_in[11], *bl2 = (const float*)d_in[12];
    const float* Wr2 = (const float*)d_in[13], *br2 = (const float*)d_in[14];
    const float* We2 = (const float*)d_in[15], *att2 = (const float*)d_in[16], *bias2 = (const float*)d_in[17];
    const float* Wl3 = (const float*)d_in[18], *bl3 = (const float*)d_in[19];
    const float* Wr3 = (const float*)d_in[20], *br3 = (const float*)d_in[21];
    const float* We3 = (const float*)d_in[22], *att3 = (const float*)d_in[23], *bias3 = (const float*)d_in[24];
    const float* mW1 = (const float*)d_in[25], *mb1 = (const float*)d_in[26];
    const float* mW2 = (const float*)d_in[27], *mb2 = (const float*)d_in[28];
    const float* mW3 = (const float*)d_in[29], *mb3 = (const float*)d_in[30];
    float* out = (float*)d_out;

    const int* srcp = ei;
    const int* dstp = ei + N_EDGES;

    float *xl, *xr, *hA, *sums;
    int *deg, *rowptr, *cursor, *csr_src, *cnt;
    float4* csr_ea;
    __nv_bfloat16 *ahi, *alo, *whL, *wlL, *whR, *wlR;
    cudaGetSymbolAddress((void**)&xl, g_xl);
    cudaGetSymbolAddress((void**)&xr, g_xr);
    cudaGetSymbolAddress((void**)&hA, g_hA);
    cudaGetSymbolAddress((void**)&sums, g_sums);
    cudaGetSymbolAddress((void**)&deg, g_deg);
    cudaGetSymbolAddress((void**)&rowptr, g_rowptr);
    cudaGetSymbolAddress((void**)&cursor, g_cursor);
    cudaGetSymbolAddress((void**)&csr_src, g_csr_src);
    cudaGetSymbolAddress((void**)&csr_ea, g_csr_ea);
    cudaGetSymbolAddress((void**)&cnt, g_cnt);
    cudaGetSymbolAddress((void**)&ahi, g_ahi);
    cudaGetSymbolAddress((void**)&alo, g_alo);
    cudaGetSymbolAddress((void**)&whL, g_whL);
    cudaGetSymbolAddress((void**)&wlL, g_wlL);
    cudaGetSymbolAddress((void**)&whR, g_whR);
    cudaGetSymbolAddress((void**)&wlR, g_wlR);

    // launches 1-4: CSR by destination (shared by all 3 layers)
    zero_i32<<<(N_NODES + 255) / 256, 256>>>(deg, N_NODES);
    hist_k<<<(N_EDGES + 255) / 256, 256>>>(dstp, deg);
    scan_k<<<1, 1024>>>(deg, rowptr, cursor);
    scatter_k<<<(N_EDGES + 255) / 256, 256>>>(srcp, dstp, (const float4*)ea, cursor, csr_src, csr_ea);

    // launch 5: layer-1 dual GEMM (xl + xr in one pass)
    gemm_k12_dual<<<(N_NODES + 31) / 32, 256>>>(x, Wl1, bl1, Wr1, br1, xl, xr);

    // launch 6: edge_agg_h4 — profiled by ncu (-s 5 -c 1)
    edge_agg_h4<<<2500, 256>>>(rowptr, csr_src, csr_ea, xl, xr, We1, att1, bias1, ahi, alo);

    // ---- layer 2 (256 -> 256, H=4) ----
    splitW_dual<<<(256 * 256 + 255) / 256, 256>>>(Wl2, Wr2, whL, wlL, whR, wlR, 256, 256);
    gemm_bf16<<<dim3(4, 157), 256>>>(ahi, alo, whL, wlL, bl2, xl, N_NODES, 256, 256);
    gemm_bf16<<<dim3(4, 157), 256>>>(ahi, alo, whR, wlR, br2, xr, N_NODES, 256, 256);
    edge_agg_h4<<<2500, 256>>>(rowptr, csr_src, csr_ea, xl, xr, We2, att2, bias2, ahi, alo);

    // ---- layer 3 (256 -> 64, H=1, no ELU) ----
    splitW_dual<<<(256 * 64 + 255) / 256, 256>>>(Wl3, Wr3, whL, wlL, whR, wlR, 256, 64);
    gemm_bf16<<<dim3(1, 157), 256>>>(ahi, alo, whL, wlL, bl3, xl, N_NODES, 256, 64);
    gemm_bf16<<<dim3(1, 157), 256>>>(ahi, alo, whR, wlR, br3, xr, N_NODES, 256, 64);
    edge_agg_h1<<<2500, 256>>>(rowptr, csr_src, csr_ea, xl, xr, We3, att3, bias3, hA);

    // ---- global mean pool + MLP head ----
    zero_f32<<<(N_GRAPHS * 64 + 255) / 256, 256>>>(sums, N_GRAPHS * 64);
    zero_i32<<<(N_GRAPHS + 255) / 256, 256>>>(cnt, N_GRAPHS);
    pool_k<<<(N_NODES * 64 + 255) / 256, 256>>>(hA, batch, sums, cnt);
    mlp_k<<<N_GRAPHS, 64>>>(sums, cnt, mW1, mb1, mW2, mb2, mW3, mb3, out);
}

// round 12
// speedup vs baseline: 1.2185x; 1.0285x over previous
#include <cuda_runtime.h>
#include <cuda_bf16.h>
#include <math.h>
#include <stdint.h>

#define N_NODES  20000
#define N_EDGES  320000
#define N_GRAPHS 1000

// ---------------- static device scratch (no allocations allowed) ----------------
__device__ float    g_xl[N_NODES * 256];
__device__ float    g_xr[N_NODES * 256];
__device__ uint16_t g_ahi[N_NODES * 256];
__device__ uint16_t g_alo[N_NODES * 256];
__device__ uint16_t g_whL[256 * 256];
__device__ uint16_t g_wlL[256 * 256];
__device__ uint16_t g_whR[256 * 256];
__device__ uint16_t g_wlR[256 * 256];
__device__ int      g_deg[N_NODES];
__device__ int      g_rowptr[N_NODES + 1];
__device__ int      g_cursor[N_NODES];
__device__ int      g_csr_src[N_EDGES];
__device__ float4   g_csr_ea[N_EDGES];
__device__ float    g_sums[N_GRAPHS * 64];
__device__ int      g_cnt[N_GRAPHS];

// ---------------- utility kernels ----------------
__global__ void zero_i32(int* p, int n) {
    int i = blockIdx.x * blockDim.x + threadIdx.x;
    if (i < n) p[i] = 0;
}
__global__ void zero_f32(float* p, int n) {
    int i = blockIdx.x * blockDim.x + threadIdx.x;
    if (i < n) p[i] = 0.f;
}
__global__ void hist_k(const int* __restrict__ dst, int* __restrict__ deg) {
    int e = blockIdx.x * blockDim.x + threadIdx.x;
    if (e < N_EDGES) atomicAdd(&deg[dst[e]], 1);
}

__global__ void scan_k(const int* __restrict__ deg, int* __restrict__ rowptr,
                       int* __restrict__ cursor) {
    __shared__ int sh[1024];
    const int CH = 20;
    int t = threadIdx.x;
    int base = t * CH;
    int loc[CH];
    int s = 0;
    #pragma unroll
    for (int i = 0; i < CH; i++) {
        int idx = base + i;
        int v = (idx < N_NODES) ? deg[idx] : 0;
        loc[i] = s;
        s += v;
    }
    sh[t] = s;
    __syncthreads();
    for (int off = 1; off < 1024; off <<= 1) {
        int v = (t >= off) ? sh[t - off] : 0;
        __syncthreads();
        sh[t] += v;
        __syncthreads();
    }
    int pre = (t > 0) ? sh[t - 1] : 0;
    #pragma unroll
    for (int i = 0; i < CH; i++) {
        int idx = base + i;
        if (idx < N_NODES) {
            int v = pre + loc[i];
            rowptr[idx] = v;
            cursor[idx] = v;
        }
    }
    if (t == 1023) rowptr[N_NODES] = sh[1023];
}

__global__ void scatter_k(const int* __restrict__ src, const int* __restrict__ dst,
                          const float4* __restrict__ ea, int* __restrict__ cursor,
                          int* __restrict__ csr_src, float4* __restrict__ csr_ea) {
    int e = blockIdx.x * blockDim.x + threadIdx.x;
    if (e < N_EDGES) {
        int p = atomicAdd(&cursor[dst[e]], 1);
        csr_src[p] = src[e];
        csr_ea[p] = ea[e];
    }
}

// dual W split: both L and R weights, W[K][Nc] fp32 -> transposed [Nc][K] bf16 hi/lo
__global__ void splitW_dual(const float* __restrict__ WL, const float* __restrict__ WR,
                            __nv_bfloat16* __restrict__ hiL, __nv_bfloat16* __restrict__ loL,
                            __nv_bfloat16* __restrict__ hiR, __nv_bfloat16* __restrict__ loR,
                            int K, int Nc) {
    int i = blockIdx.x * blockDim.x + threadIdx.x;
    if (i < K * Nc) {
        int k = i / Nc, n = i - k * Nc;
        float v = WL[i];
        __nv_bfloat16 h = __float2bfloat16(v);
        hiL[(size_t)n * K + k] = h;
        loL[(size_t)n * K + k] = __float2bfloat16(v - __bfloat162float(h));
        v = WR[i];
        h = __float2bfloat16(v);
        hiR[(size_t)n * K + k] = h;
        loR[(size_t)n * K + k] = __float2bfloat16(v - __bfloat162float(h));
    }
}

// ---------------- layer-1 dual GEMM (K=12 -> 256 for both Wl and Wr) ----------------
__global__ void gemm_k12_dual(const float* __restrict__ x,
                              const float* __restrict__ WL, const float* __restrict__ bL,
                              const float* __restrict__ WR, const float* __restrict__ bR,
                              float* __restrict__ xl, float* __restrict__ xr) {
    __shared__ float WsL[12 * 256];
    __shared__ float WsR[12 * 256];
    __shared__ float xs[32 * 12];
    int tid = threadIdx.x;
    int r0 = blockIdx.x * 32;
    for (int i = tid; i < 12 * 256; i += 256) {
        WsL[i] = WL[i];
        WsR[i] = WR[i];
    }
    for (int i = tid; i < 32 * 12; i += 256) {
        int r = r0 + i / 12;
        xs[i] = (r < N_NODES) ? x[(size_t)r * 12 + (i % 12)] : 0.f;
    }
    __syncthreads();
    float bbL = bL[tid], bbR = bR[tid];
    for (int r = 0; r < 32; r++) {
        int gr = r0 + r;
        if (gr >= N_NODES) break;
        float accL = bbL, accR = bbR;
        #pragma unroll
        for (int k = 0; k < 12; k++) {
            float xv = xs[r * 12 + k];
            accL += xv * WsL[k * 256 + tid];
            accR += xv * WsR[k * 256 + tid];
        }
        xl[(size_t)gr * 256 + tid] = accL;
        xr[(size_t)gr * 256 + tid] = accR;
    }
}

// ---------------- bf16 mma.sync GEMM with pre-split hi/lo (3-term) ----------------
__device__ __forceinline__ uint32_t smem_u32(const void* p) {
    uint32_t a;
    asm("{ .reg .u64 t; cvta.to.shared.u64 t, %1; cvt.u32.u64 %0, t; }" : "=r"(a) : "l"(p));
    return a;
}
#define LDSM_X4(r0, r1, r2, r3, addr) \
    asm volatile("ldmatrix.sync.aligned.m8n8.x4.shared.b16 {%0,%1,%2,%3}, [%4];" \
                 : "=r"(r0), "=r"(r1), "=r"(r2), "=r"(r3) : "r"(addr))
#define LDSM_X2(r0, r1, addr) \
    asm volatile("ldmatrix.sync.aligned.m8n8.x2.shared.b16 {%0,%1}, [%2];" \
                 : "=r"(r0), "=r"(r1) : "r"(addr))
__device__ __forceinline__ void mma_bf16(float* d, uint32_t a0, uint32_t a1,
                                         uint32_t a2, uint32_t a3,
                                         uint32_t b0, uint32_t b1) {
    asm volatile(
        "mma.sync.aligned.m16n8k16.row.col.f32.bf16.bf16.f32 "
        "{%0,%1,%2,%3},{%4,%5,%6,%7},{%8,%9},{%0,%1,%2,%3};"
        : "+f"(d[0]), "+f"(d[1]), "+f"(d[2]), "+f"(d[3])
        : "r"(a0), "r"(a1), "r"(a2), "r"(a3), "r"(b0), "r"(b1));
}

// C[M,Ncols] = A @ W + bias. BM=128, BN=64, BK=32. 256 threads = 8 warps.
__global__ __launch_bounds__(256) void gemm_bf16(
    const __nv_bfloat16* __restrict__ Ahi, const __nv_bfloat16* __restrict__ Alo,
    const __nv_bfloat16* __restrict__ BhiT, const __nv_bfloat16* __restrict__ BloT,
    const float* __restrict__ bias, float* __restrict__ C, int M, int K, int Ncols) {
    const int SA = 40;
    __shared__ __align__(16) uint16_t As_h[128 * 40];
    __shared__ __align__(16) uint16_t As_l[128 * 40];
    __shared__ __align__(16) uint16_t Bs_h[64 * 40];
    __shared__ __align__(16) uint16_t Bs_l[64 * 40];

    int tid = threadIdx.x, lane = tid & 31, warp = tid >> 5;
    int warpM = warp & 3, warpN = warp >> 2;
    int row0 = blockIdx.y * 128, col0 = blockIdx.x * 64;

    float acc[2][4][4];
    #pragma unroll
    for (int mt = 0; mt < 2; mt++)
        #pragma unroll
        for (int nt = 0; nt < 4; nt++)
            #pragma unroll
            for (int i = 0; i < 4; i++) acc[mt][nt][i] = 0.f;

    uint32_t aadH[2], aadL[2], badH[4], badL[4];
    {
        int ar = (lane & 7) + ((lane >> 3) & 1) * 8;
        int ac = (lane >> 4) * 8;
        #pragma unroll
        for (int mt = 0; mt < 2; mt++) {
            int r = warpM * 32 + mt * 16 + ar;
            aadH[mt] = smem_u32(As_h) + (uint32_t)(r * SA + ac) * 2;
            aadL[mt] = smem_u32(As_l) + (uint32_t)(r * SA + ac) * 2;
        }
        int l16 = lane & 15;
        int bn = l16 & 7;
        int bc = ((l16 >> 3) & 1) * 8;
        #pragma unroll
        for (int nt = 0; nt < 4; nt++) {
            int n = warpN * 32 + nt * 8 + bn;
            badH[nt] = smem_u32(Bs_h) + (uint32_t)(n * SA + bc) * 2;
            badL[nt] = smem_u32(Bs_l) + (uint32_t)(n * SA + bc) * 2;
        }
    }

    for (int k0 = 0; k0 < K; k0 += 32) {
        #pragma unroll
        for (int it = 0; it < 2; it++) {
            int idx = tid + it * 256;
            int r = idx >> 2, sk = (idx & 3) * 8;
            int grow = row0 + r;
            uint4 vh = make_uint4(0, 0, 0, 0), vl = make_uint4(0, 0, 0, 0);
            if (grow < M) {
                size_t off = (size_t)grow * K + k0 + sk;
                vh = *(const uint4*)(Ahi + off);
                vl = *(const uint4*)(Alo + off);
            }
            *(uint4*)&As_h[r * SA + sk] = vh;
            *(uint4*)&As_l[r * SA + sk] = vl;
        }
        {
            int r = tid >> 2, sk = (tid & 3) * 8;
            size_t off = (size_t)(col0 + r) * K + k0 + sk;
            *(uint4*)&Bs_h[r * SA + sk] = *(const uint4*)(BhiT + off);
            *(uint4*)&Bs_l[r * SA + sk] = *(const uint4*)(BloT + off);
        }
        __syncthreads();

        #pragma unroll
        for (int ks = 0; ks < 32; ks += 16) {
            uint32_t kb = ks * 2;
            uint32_t ah[2][4], al[2][4], bh[4][2], bl[4][2];
            #pragma unroll
            for (int mt = 0; mt < 2; mt++) {
                LDSM_X4(ah[mt][0], ah[mt][1], ah[mt][2], ah[mt][3], aadH[mt] + kb);
                LDSM_X4(al[mt][0], al[mt][1], al[mt][2], al[mt][3], aadL[mt] + kb);
            }
            #pragma unroll
            for (int nt = 0; nt < 4; nt++) {
                LDSM_X2(bh[nt][0], bh[nt][1], badH[nt] + kb);
                LDSM_X2(bl[nt][0], bl[nt][1], badL[nt] + kb);
            }
            #pragma unroll
            for (int mt = 0; mt < 2; mt++)
                #pragma unroll
                for (int nt = 0; nt < 4; nt++) {
                    mma_bf16(acc[mt][nt], ah[mt][0], ah[mt][1], ah[mt][2], ah[mt][3],
                             bl[nt][0], bl[nt][1]);
                    mma_bf16(acc[mt][nt], al[mt][0], al[mt][1], al[mt][2], al[mt][3],
                             bh[nt][0], bh[nt][1]);
                    mma_bf16(acc[mt][nt], ah[mt][0], ah[mt][1], ah[mt][2], ah[mt][3],
                             bh[nt][0], bh[nt][1]);
                }
        }
        __syncthreads();
    }

    int g = lane >> 2, tg = lane & 3;
    #pragma unroll
    for (int nt = 0; nt < 4; nt++) {
        int col = col0 + warpN * 32 + nt * 8 + 2 * tg;
        float2 bv = *(const float2*)(bias + col);
        #pragma unroll
        for (int mt = 0; mt < 2; mt++) {
            int r = row0 + warpM * 32 + mt * 16 + g;
            if (r < M) {
                float2 v = make_float2(acc[mt][nt][0] + bv.x, acc[mt][nt][1] + bv.y);
                *(float2*)(C + (size_t)r * Ncols + col) = v;
            }
            if (r + 8 < M) {
                float2 v = make_float2(acc[mt][nt][2] + bv.x, acc[mt][nt][3] + bv.y);
                *(float2*)(C + (size_t)(r + 8) * Ncols + col) = v;
            }
        }
    }
}

// ---------------- fused edge aggregation, H=4: ONE warp per node, pipelined --------
// lane owns 8 contiguous channels; per-head 3-SHFL butterfly. 2-edge unroll with
// 1-deep prefetch of next iteration's csr_src/csr_ea (breaks the idx->xl chain).
__global__ void edge_agg_h4(const int* __restrict__ rowptr, const int* __restrict__ csr_src,
                            const float4* __restrict__ csr_ea,
                            const float* __restrict__ xl, const float* __restrict__ xr,
                            const float* __restrict__ We, const float* __restrict__ att,
                            const float* __restrict__ bias,
                            __nv_bfloat16* __restrict__ out_hi,
                            __nv_bfloat16* __restrict__ out_lo) {
    int w = (blockIdx.x * blockDim.x + threadIdx.x) >> 5;  // node
    int lane = threadIdx.x & 31;
    if (w >= N_NODES) return;
    int n = w;
    int c = lane * 8;

    float xrv[8], atv[8], wev[4][8];
    {
        float4 v0 = *(const float4*)(xr + (size_t)n * 256 + c);
        float4 v1 = *(const float4*)(xr + (size_t)n * 256 + c + 4);
        xrv[0] = v0.x; xrv[1] = v0.y; xrv[2] = v0.z; xrv[3] = v0.w;
        xrv[4] = v1.x; xrv[5] = v1.y; xrv[6] = v1.z; xrv[7] = v1.w;
        v0 = *(const float4*)(att + c);
        v1 = *(const float4*)(att + c + 4);
        atv[0] = v0.x; atv[1] = v0.y; atv[2] = v0.z; atv[3] = v0.w;
        atv[4] = v1.x; atv[5] = v1.y; atv[6] = v1.z; atv[7] = v1.w;
        #pragma unroll
        for (int f = 0; f < 4; f++) {
            v0 = *(const float4*)(We + f * 256 + c);
            v1 = *(const float4*)(We + f * 256 + c + 4);
            wev[f][0] = v0.x; wev[f][1] = v0.y; wev[f][2] = v0.z; wev[f][3] = v0.w;
            wev[f][4] = v1.x; wev[f][5] = v1.y; wev[f][6] = v1.z; wev[f][7] = v1.w;
        }
    }

    float s = 0.f, a[8];
    #pragma unroll
    for (int j = 0; j < 8; j++) a[j] = 0.f;
    int beg = rowptr[n], end = rowptr[n + 1];

    // 1-deep prefetch of the next pair of (src, ea)
    int sn0 = 0, sn1 = 0;
    float4 e0 = make_float4(0, 0, 0, 0), e1 = e0;
    if (beg + 1 < end) {
        sn0 = csr_src[beg];
        sn1 = csr_src[beg + 1];
        e0 = csr_ea[beg];
        e1 = csr_ea[beg + 1];
    }

    int i = beg;
    for (; i + 1 < end; i += 2) {
        int csn0 = sn0, csn1 = sn1;
        float4 ce0 = e0, ce1 = e1;
        if (i + 3 < end) {
            sn0 = csr_src[i + 2];
            sn1 = csr_src[i + 3];
            e0 = csr_ea[i + 2];
            e1 = csr_ea[i + 3];
        }
        float4 xa0 = *(const float4*)(xl + (size_t)csn0 * 256 + c);
        float4 xb0 = *(const float4*)(xl + (size_t)csn0 * 256 + c + 4);
        float4 xa1 = *(const float4*)(xl + (size_t)csn1 * 256 + c);
        float4 xb1 = *(const float4*)(xl + (size_t)csn1 * 256 + c + 4);
        float x0[8] = {xa0.x, xa0.y, xa0.z, xa0.w, xb0.x, xb0.y, xb0.z, xb0.w};
        float x1[8] = {xa1.x, xa1.y, xa1.z, xa1.w, xb1.x, xb1.y, xb1.z, xb1.w};

        float t0 = 0.f, t1 = 0.f;
        #pragma unroll
        for (int j = 0; j < 8; j++) {
            float z0 = x0[j] + xrv[j] + ce0.x * wev[0][j] + ce0.y * wev[1][j]
                       + ce0.z * wev[2][j] + ce0.w * wev[3][j];
            float z1 = x1[j] + xrv[j] + ce1.x * wev[0][j] + ce1.y * wev[1][j]
                       + ce1.z * wev[2][j] + ce1.w * wev[3][j];
            z0 = z0 > 0.f ? z0 : 0.2f * z0;
            z1 = z1 > 0.f ? z1 : 0.2f * z1;
            t0 += z0 * atv[j];
            t1 += z1 * atv[j];
        }
        #pragma unroll
        for (int o = 4; o > 0; o >>= 1) {
            t0 += __shfl_xor_sync(0xFFFFFFFFu, t0, o);
            t1 += __shfl_xor_sync(0xFFFFFFFFu, t1, o);
        }
        float p0 = __expf(t0), p1 = __expf(t1);
        s += p0 + p1;
        #pragma unroll
        for (int j = 0; j < 8; j++) a[j] += p0 * x0[j] + p1 * x1[j];
    }
    if (i < end) {
        int sn = csr_src[i];
        float4 eav = csr_ea[i];
        float4 xa = *(const float4*)(xl + (size_t)sn * 256 + c);
        float4 xb = *(const float4*)(xl + (size_t)sn * 256 + c + 4);
        float xv[8] = {xa.x, xa.y, xa.z, xa.w, xb.x, xb.y, xb.z, xb.w};
        float t = 0.f;
        #pragma unroll
        for (int j = 0; j < 8; j++) {
            float z = xv[j] + xrv[j] + eav.x * wev[0][j] + eav.y * wev[1][j]
                      + eav.z * wev[2][j] + eav.w * wev[3][j];
            z = z > 0.f ? z : 0.2f * z;
            t += z * atv[j];
        }
        #pragma unroll
        for (int o = 4; o > 0; o >>= 1) t += __shfl_xor_sync(0xFFFFFFFFu, t, o);
        float p = __expf(t);
        s += p;
        #pragma unroll
        for (int j = 0; j < 8; j++) a[j] += p * xv[j];
    }

    float inv = 1.f / (s + 1e-16f);
    float4 bv0 = *(const float4*)(bias + c);
    float4 bv1 = *(const float4*)(bias + c + 4);
    float bb[8] = {bv0.x, bv0.y, bv0.z, bv0.w, bv1.x, bv1.y, bv1.z, bv1.w};
    uint16_t hv[8], lv[8];
    #pragma unroll
    for (int j = 0; j < 8; j++) {
        float r = a[j] * inv + bb[j];
        r = r > 0.f ? r : expm1f(r);   // ELU
        __nv_bfloat16 h = __float2bfloat16(r);
        __nv_bfloat16 l = __float2bfloat16(r - __bfloat162float(h));
        hv[j] = *(uint16_t*)&h;
        lv[j] = *(uint16_t*)&l;
    }
    *(uint4*)(out_hi + (size_t)n * 256 + c) = *(uint4*)hv;
    *(uint4*)(out_lo + (size_t)n * 256 + c) = *(uint4*)lv;
}

// ---------------- edge aggregation, H=1 (layer 3) + fused global-mean-pool --------
// R8 config; epilogue atomically accumulates into per-graph sums/cnt (no hA pass).
__global__ void edge_agg_h1_pool(const int* __restrict__ rowptr, const int* __restrict__ csr_src,
                                 const float4* __restrict__ csr_ea,
                                 const float* __restrict__ xl, const float* __restrict__ xr,
                                 const float* __restrict__ We, const float* __restrict__ att,
                                 const float* __restrict__ bias, const int* __restrict__ batch,
                                 float* __restrict__ sums, int* __restrict__ cnt) {
    const int D = 64;
    int w = (blockIdx.x * blockDim.x + threadIdx.x) >> 5;
    int lane = threadIdx.x & 31;
    int n = w;
    if (n >= N_NODES) return;

    int c = 2 * lane;
    float2 xrv = *(const float2*)(xr + (size_t)n * D + c);
    float2 atv = *(const float2*)(att + c);
    float2 wev[4];
    #pragma unroll
    for (int f = 0; f < 4; f++) wev[f] = *(const float2*)(We + f * D + c);

    float s0 = 0.f, a00 = 0.f, a01 = 0.f;
    float s1 = 0.f, a10 = 0.f, a11 = 0.f;
    int beg = rowptr[n], end = rowptr[n + 1];

    int i = beg;
    for (; i + 3 < end; i += 4) {
        int sn0 = csr_src[i], sn1 = csr_src[i + 1], sn2 = csr_src[i + 2], sn3 = csr_src[i + 3];
        float4 e0 = csr_ea[i], e1 = csr_ea[i + 1], e2 = csr_ea[i + 2], e3 = csr_ea[i + 3];
        float2 x0 = *(const float2*)(xl + (size_t)sn0 * D + c);
        float2 x1 = *(const float2*)(xl + (size_t)sn1 * D + c);
        float2 x2 = *(const float2*)(xl + (size_t)sn2 * D + c);
        float2 x3 = *(const float2*)(xl + (size_t)sn3 * D + c);

        float za, zb, t0, t1, t2, t3;
        za = x0.x + xrv.x + e0.x * wev[0].x + e0.y * wev[1].x + e0.z * wev[2].x + e0.w * wev[3].x;
        zb = x0.y + xrv.y + e0.x * wev[0].y + e0.y * wev[1].y + e0.z * wev[2].y + e0.w * wev[3].y;
        za = za > 0.f ? za : 0.2f * za; zb = zb > 0.f ? zb : 0.2f * zb;
        t0 = za * atv.x + zb * atv.y;
        za = x1.x + xrv.x + e1.x * wev[0].x + e1.y * wev[1].x + e1.z * wev[2].x + e1.w * wev[3].x;
        zb = x1.y + xrv.y + e1.x * wev[0].y + e1.y * wev[1].y + e1.z * wev[2].y + e1.w * wev[3].y;
        za = za > 0.f ? za : 0.2f * za; zb = zb > 0.f ? zb : 0.2f * zb;
        t1 = za * atv.x + zb * atv.y;
        za = x2.x + xrv.x + e2.x * wev[0].x + e2.y * wev[1].x + e2.z * wev[2].x + e2.w * wev[3].x;
        zb = x2.y + xrv.y + e2.x * wev[0].y + e2.y * wev[1].y + e2.z * wev[2].y + e2.w * wev[3].y;
        za = za > 0.f ? za : 0.2f * za; zb = zb > 0.f ? zb : 0.2f * zb;
        t2 = za * atv.x + zb * atv.y;
        za = x3.x + xrv.x + e3.x * wev[0].x + e3.y * wev[1].x + e3.z * wev[2].x + e3.w * wev[3].x;
        zb = x3.y + xrv.y + e3.x * wev[0].y + e3.y * wev[1].y + e3.z * wev[2].y + e3.w * wev[3].y;
        za = za > 0.f ? za : 0.2f * za; zb = zb > 0.f ? zb : 0.2f * zb;
        t3 = za * atv.x + zb * atv.y;

        #pragma unroll
        for (int o = 16; o > 0; o >>= 1) {
            t0 += __shfl_xor_sync(0xFFFFFFFFu, t0, o);
            t1 += __shfl_xor_sync(0xFFFFFFFFu, t1, o);
            t2 += __shfl_xor_sync(0xFFFFFFFFu, t2, o);
            t3 += __shfl_xor_sync(0xFFFFFFFFu, t3, o);
        }
        float p0 = __expf(t0), p1 = __expf(t1), p2 = __expf(t2), p3 = __expf(t3);
        s0 += p0; a00 += p0 * x0.x; a01 += p0 * x0.y;
        s1 += p1; a10 += p1 * x1.x; a11 += p1 * x1.y;
        s0 += p2; a00 += p2 * x2.x; a01 += p2 * x2.y;
        s1 += p3; a10 += p3 * x3.x; a11 += p3 * x3.y;
    }
    for (; i < end; i++) {
        int sn = csr_src[i];
        float4 eav = csr_ea[i];
        float2 xv = *(const float2*)(xl + (size_t)sn * D + c);
        float z0 = xv.x + xrv.x + eav.x * wev[0].x + eav.y * wev[1].x + eav.z * wev[2].x + eav.w * wev[3].x;
        float z1 = xv.y + xrv.y + eav.x * wev[0].y + eav.y * wev[1].y + eav.z * wev[2].y + eav.w * wev[3].y;
        z0 = z0 > 0.f ? z0 : 0.2f * z0;
        z1 = z1 > 0.f ? z1 : 0.2f * z1;
        float t = z0 * atv.x + z1 * atv.y;
        #pragma unroll
        for (int o = 16; o > 0; o >>= 1) t += __shfl_xor_sync(0xFFFFFFFFu, t, o);
        float p = __expf(t);
        s0 += p; a00 += p * xv.x; a01 += p * xv.y;
    }
    float s = s0 + s1;
    float a0 = a00 + a10;
    float a1 = a01 + a11;

    float inv = 1.f / (s + 1e-16f);
    float2 bv = *(const float2*)(bias + c);
    float r0 = a0 * inv + bv.x;
    float r1 = a1 * inv + bv.y;

    // fused pool: accumulate into per-graph sums
    int g = batch[n];
    atomicAdd(&sums[g * 64 + c], r0);
    atomicAdd(&sums[g * 64 + c + 1], r1);
    if (lane == 0) atomicAdd(&cnt[g], 1);
}

// ---------------- MLP head ----------------
__global__ void mlp_k(const float* __restrict__ sums, const int* __restrict__ cnt,
                      const float* __restrict__ mW1, const float* __restrict__ mb1,
                      const float* __restrict__ mW2, const float* __restrict__ mb2,
                      const float* __restrict__ mW3, const float* __restrict__ mb3,
                      float* __restrict__ out) {
    __shared__ float gv[64];
    __shared__ float h1[32];
    __shared__ float h2[16];
    int g = blockIdx.x, t = threadIdx.x;
    float cf = fmaxf((float)cnt[g], 1.f);
    gv[t] = sums[g * 64 + t] / cf;
    __syncthreads();
    if (t < 32) {
        float a = mb1[t];
        #pragma unroll
        for (int k = 0; k < 64; k++) a += gv[k] * mW1[k * 32 + t];
        h1[t] = fmaxf(a, 0.f);
    }
    __syncthreads();
    if (t < 16) {
        float a = mb2[t];
        #pragma unroll
        for (int k = 0; k < 32; k++) a += h1[k] * mW2[k * 16 + t];
        h2[t] = fmaxf(a, 0.f);
    }
    __syncthreads();
    if (t < 4) {
        float a = mb3[t];
        #pragma unroll
        for (int k = 0; k < 16; k++) a += h2[k] * mW3[k * 4 + t];
        out[g * 4 + t] = a;
    }
}

// ---------------- launch ----------------
extern "C" void kernel_launch(void* const* d_in, const int* in_sizes, int n_in,
                              void* d_out, int out_size) {
    (void)in_sizes; (void)n_in; (void)out_size;
    const float* x     = (const float*)d_in[0];
    const int*   ei    = (const int*)d_in[1];
    const float* ea    = (const float*)d_in[2];
    const int*   batch = (const int*)d_in[3];
    const float* Wl1 = (const float*)d_in[4],  *bl1 = (const float*)d_in[5];
    const float* Wr1 = (const float*)d_in[6],  *br1 = (const float*)d_in[7];
    const float* We1 = (const float*)d_in[8],  *att1 = (const float*)d_in[9],  *bias1 = (const float*)d_in[10];
    const float* Wl2 = (const float*)d_in[11], *bl2 = (const float*)d_in[12];
    const float* Wr2 = (const float*)d_in[13], *br2 = (const float*)d_in[14];
    const float* We2 = (const float*)d_in[15], *att2 = (const float*)d_in[16], *bias2 = (const float*)d_in[17];
    const float* Wl3 = (const float*)d_in[18], *bl3 = (const float*)d_in[19];
    const float* Wr3 = (const float*)d_in[20], *br3 = (const float*)d_in[21];
    const float* We3 = (const float*)d_in[22], *att3 = (const float*)d_in[23], *bias3 = (const float*)d_in[24];
    const float* mW1 = (const float*)d_in[25], *mb1 = (const float*)d_in[26];
    const float* mW2 = (const float*)d_in[27], *mb2 = (const float*)d_in[28];
    const float* mW3 = (const float*)d_in[29], *mb3 = (const float*)d_in[30];
    float* out = (float*)d_out;

    const int* srcp = ei;
    const int* dstp = ei + N_EDGES;

    float *xl, *xr, *sums;
    int *deg, *rowptr, *cursor, *csr_src, *cnt;
    float4* csr_ea;
    __nv_bfloat16 *ahi, *alo, *whL, *wlL, *whR, *wlR;
    cudaGetSymbolAddress((void**)&xl, g_xl);
    cudaGetSymbolAddress((void**)&xr, g_xr);
    cudaGetSymbolAddress((void**)&sums, g_sums);
    cudaGetSymbolAddress((void**)&deg, g_deg);
    cudaGetSymbolAddress((void**)&rowptr, g_rowptr);
    cudaGetSymbolAddress((void**)&cursor, g_cursor);
    cudaGetSymbolAddress((void**)&csr_src, g_csr_src);
    cudaGetSymbolAddress((void**)&csr_ea, g_csr_ea);
    cudaGetSymbolAddress((void**)&cnt, g_cnt);
    cudaGetSymbolAddress((void**)&ahi, g_ahi);
    cudaGetSymbolAddress((void**)&alo, g_alo);
    cudaGetSymbolAddress((void**)&whL, g_whL);
    cudaGetSymbolAddress((void**)&wlL, g_wlL);
    cudaGetSymbolAddress((void**)&whR, g_whR);
    cudaGetSymbolAddress((void**)&wlR, g_wlR);

    // launches 1-4: CSR by destination (shared by all 3 layers)
    zero_i32<<<(N_NODES + 255) / 256, 256>>>(deg, N_NODES);
    hist_k<<<(N_EDGES + 255) / 256, 256>>>(dstp, deg);
    scan_k<<<1, 1024>>>(deg, rowptr, cursor);
    scatter_k<<<(N_EDGES + 255) / 256, 256>>>(srcp, dstp, (const float4*)ea, cursor, csr_src, csr_ea);

    // launch 5: layer-1 dual GEMM (xl + xr in one pass)
    gemm_k12_dual<<<(N_NODES + 31) / 32, 256>>>(x, Wl1, bl1, Wr1, br1, xl, xr);

    // launch 6: edge_agg_h4 — profiled by ncu (-s 5 -c 1)
    edge_agg_h4<<<2500, 256>>>(rowptr, csr_src, csr_ea, xl, xr, We1, att1, bias1, ahi, alo);

    // ---- layer 2 (256 -> 256, H=4) ----
    splitW_dual<<<(256 * 256 + 255) / 256, 256>>>(Wl2, Wr2, whL, wlL, whR, wlR, 256, 256);
    gemm_bf16<<<dim3(4, 157), 256>>>(ahi, alo, whL, wlL, bl2, xl, N_NODES, 256, 256);
    gemm_bf16<<<dim3(4, 157), 256>>>(ahi, alo, whR, wlR, br2, xr, N_NODES, 256, 256);
    edge_agg_h4<<<2500, 256>>>(rowptr, csr_src, csr_ea, xl, xr, We2, att2, bias2, ahi, alo);

    // ---- layer 3 (256 -> 64, H=1, no ELU), pool fused into epilogue ----
    splitW_dual<<<(256 * 64 + 255) / 256, 256>>>(Wl3, Wr3, whL, wlL, whR, wlR, 256, 64);
    gemm_bf16<<<dim3(1, 157), 256>>>(ahi, alo, whL, wlL, bl3, xl, N_NODES, 256, 64);
    gemm_bf16<<<dim3(1, 157), 256>>>(ahi, alo, whR, wlR, br3, xr, N_NODES, 256, 64);
    zero_f32<<<(N_GRAPHS * 64 + 255) / 256, 256>>>(sums, N_GRAPHS * 64);
    zero_i32<<<(N_GRAPHS + 255) / 256, 256>>>(cnt, N_GRAPHS);
    edge_agg_h1_pool<<<2500, 256>>>(rowptr, csr_src, csr_ea, xl, xr, We3, att3, bias3,
                                    batch, sums, cnt);

    // ---- MLP head ----
    mlp_k<<<N_GRAPHS, 64>>>(sums, cnt, mW1, mb1, mW2, mb2, mW3, mb3, out);
}

// round 13
// speedup vs baseline: 1.2971x; 1.0645x over previous
#include <cuda_runtime.h>
#include <cuda_bf16.h>
#include <math.h>
#include <stdint.h>

#define N_NODES  20000
#define N_EDGES  320000
#define N_GRAPHS 1000

// ---------------- static device scratch (no allocations allowed) ----------------
__device__ float    g_xl[N_NODES * 256];
__device__ float    g_xr[N_NODES * 256];
__device__ uint16_t g_ahi[N_NODES * 256];
__device__ uint16_t g_alo[N_NODES * 256];
__device__ uint16_t g_whL[256 * 256];
__device__ uint16_t g_wlL[256 * 256];
__device__ uint16_t g_whR[256 * 256];
__device__ uint16_t g_wlR[256 * 256];
__device__ int      g_deg[N_NODES];
__device__ int      g_rowptr[N_NODES + 1];
__device__ int      g_cursor[N_NODES];
__device__ int      g_csr_src[N_EDGES];
__device__ float4   g_csr_ea[N_EDGES];
__device__ float    g_sums[N_GRAPHS * 64];
__device__ int      g_cnt[N_GRAPHS];

// ---------------- utility kernels ----------------
__global__ void zero_i32(int* p, int n) {
    int i = blockIdx.x * blockDim.x + threadIdx.x;
    if (i < n) p[i] = 0;
}
__global__ void zero_f32(float* p, int n) {
    int i = blockIdx.x * blockDim.x + threadIdx.x;
    if (i < n) p[i] = 0.f;
}
__global__ void hist_k(const int* __restrict__ dst, int* __restrict__ deg) {
    int e = blockIdx.x * blockDim.x + threadIdx.x;
    if (e < N_EDGES) atomicAdd(&deg[dst[e]], 1);
}

__global__ void scan_k(const int* __restrict__ deg, int* __restrict__ rowptr,
                       int* __restrict__ cursor) {
    __shared__ int sh[1024];
    const int CH = 20;
    int t = threadIdx.x;
    int base = t * CH;
    int loc[CH];
    int s = 0;
    #pragma unroll
    for (int i = 0; i < CH; i++) {
        int idx = base + i;
        int v = (idx < N_NODES) ? deg[idx] : 0;
        loc[i] = s;
        s += v;
    }
    sh[t] = s;
    __syncthreads();
    for (int off = 1; off < 1024; off <<= 1) {
        int v = (t >= off) ? sh[t - off] : 0;
        __syncthreads();
        sh[t] += v;
        __syncthreads();
    }
    int pre = (t > 0) ? sh[t - 1] : 0;
    #pragma unroll
    for (int i = 0; i < CH; i++) {
        int idx = base + i;
        if (idx < N_NODES) {
            int v = pre + loc[i];
            rowptr[idx] = v;
            cursor[idx] = v;
        }
    }
    if (t == 1023) rowptr[N_NODES] = sh[1023];
}

__global__ void scatter_k(const int* __restrict__ src, const int* __restrict__ dst,
                          const float4* __restrict__ ea, int* __restrict__ cursor,
                          int* __restrict__ csr_src, float4* __restrict__ csr_ea) {
    int e = blockIdx.x * blockDim.x + threadIdx.x;
    if (e < N_EDGES) {
        int p = atomicAdd(&cursor[dst[e]], 1);
        csr_src[p] = src[e];
        csr_ea[p] = ea[e];
    }
}

// dual W split: both L and R weights, W[K][Nc] fp32 -> transposed [Nc][K] bf16 hi/lo
__global__ void splitW_dual(const float* __restrict__ WL, const float* __restrict__ WR,
                            __nv_bfloat16* __restrict__ hiL, __nv_bfloat16* __restrict__ loL,
                            __nv_bfloat16* __restrict__ hiR, __nv_bfloat16* __restrict__ loR,
                            int K, int Nc) {
    int i = blockIdx.x * blockDim.x + threadIdx.x;
    if (i < K * Nc) {
        int k = i / Nc, n = i - k * Nc;
        float v = WL[i];
        __nv_bfloat16 h = __float2bfloat16(v);
        hiL[(size_t)n * K + k] = h;
        loL[(size_t)n * K + k] = __float2bfloat16(v - __bfloat162float(h));
        v = WR[i];
        h = __float2bfloat16(v);
        hiR[(size_t)n * K + k] = h;
        loR[(size_t)n * K + k] = __float2bfloat16(v - __bfloat162float(h));
    }
}

// ---------------- layer-1 dual GEMM (K=12 -> 256 for both Wl and Wr) ----------------
__global__ void gemm_k12_dual(const float* __restrict__ x,
                              const float* __restrict__ WL, const float* __restrict__ bL,
                              const float* __restrict__ WR, const float* __restrict__ bR,
                              float* __restrict__ xl, float* __restrict__ xr) {
    __shared__ float WsL[12 * 256];
    __shared__ float WsR[12 * 256];
    __shared__ float xs[32 * 12];
    int tid = threadIdx.x;
    int r0 = blockIdx.x * 32;
    for (int i = tid; i < 12 * 256; i += 256) {
        WsL[i] = WL[i];
        WsR[i] = WR[i];
    }
    for (int i = tid; i < 32 * 12; i += 256) {
        int r = r0 + i / 12;
        xs[i] = (r < N_NODES) ? x[(size_t)r * 12 + (i % 12)] : 0.f;
    }
    __syncthreads();
    float bbL = bL[tid], bbR = bR[tid];
    for (int r = 0; r < 32; r++) {
        int gr = r0 + r;
        if (gr >= N_NODES) break;
        float accL = bbL, accR = bbR;
        #pragma unroll
        for (int k = 0; k < 12; k++) {
            float xv = xs[r * 12 + k];
            accL += xv * WsL[k * 256 + tid];
            accR += xv * WsR[k * 256 + tid];
        }
        xl[(size_t)gr * 256 + tid] = accL;
        xr[(size_t)gr * 256 + tid] = accR;
    }
}

// ---------------- bf16 mma.sync GEMM with pre-split hi/lo (3-term) ----------------
// Dual variant: blockIdx.z selects (B, bias, C) operand set; A shared.
__device__ __forceinline__ uint32_t smem_u32(const void* p) {
    uint32_t a;
    asm("{ .reg .u64 t; cvta.to.shared.u64 t, %1; cvt.u32.u64 %0, t; }" : "=r"(a) : "l"(p));
    return a;
}
#define LDSM_X4(r0, r1, r2, r3, addr) \
    asm volatile("ldmatrix.sync.aligned.m8n8.x4.shared.b16 {%0,%1,%2,%3}, [%4];" \
                 : "=r"(r0), "=r"(r1), "=r"(r2), "=r"(r3) : "r"(addr))
#define LDSM_X2(r0, r1, addr) \
    asm volatile("ldmatrix.sync.aligned.m8n8.x2.shared.b16 {%0,%1}, [%2];" \
                 : "=r"(r0), "=r"(r1) : "r"(addr))
__device__ __forceinline__ void mma_bf16(float* d, uint32_t a0, uint32_t a1,
                                         uint32_t a2, uint32_t a3,
                                         uint32_t b0, uint32_t b1) {
    asm volatile(
        "mma.sync.aligned.m16n8k16.row.col.f32.bf16.bf16.f32 "
        "{%0,%1,%2,%3},{%4,%5,%6,%7},{%8,%9},{%0,%1,%2,%3};"
        : "+f"(d[0]), "+f"(d[1]), "+f"(d[2]), "+f"(d[3])
        : "r"(a0), "r"(a1), "r"(a2), "r"(a3), "r"(b0), "r"(b1));
}

__global__ __launch_bounds__(256) void gemm_bf16_dual(
    const __nv_bfloat16* __restrict__ Ahi, const __nv_bfloat16* __restrict__ Alo,
    const __nv_bfloat16* __restrict__ BhiL, const __nv_bfloat16* __restrict__ BloL,
    const __nv_bfloat16* __restrict__ BhiR, const __nv_bfloat16* __restrict__ BloR,
    const float* __restrict__ biasL, const float* __restrict__ biasR,
    float* __restrict__ CL, float* __restrict__ CR, int M, int K, int Ncols) {
    const int SA = 40;
    __shared__ __align__(16) uint16_t As_h[128 * 40];
    __shared__ __align__(16) uint16_t As_l[128 * 40];
    __shared__ __align__(16) uint16_t Bs_h[64 * 40];
    __shared__ __align__(16) uint16_t Bs_l[64 * 40];

    const __nv_bfloat16* BhiT = blockIdx.z ? BhiR : BhiL;
    const __nv_bfloat16* BloT = blockIdx.z ? BloR : BloL;
    const float* bias = blockIdx.z ? biasR : biasL;
    float* C = blockIdx.z ? CR : CL;

    int tid = threadIdx.x, lane = tid & 31, warp = tid >> 5;
    int warpM = warp & 3, warpN = warp >> 2;
    int row0 = blockIdx.y * 128, col0 = blockIdx.x * 64;

    float acc[2][4][4];
    #pragma unroll
    for (int mt = 0; mt < 2; mt++)
        #pragma unroll
        for (int nt = 0; nt < 4; nt++)
            #pragma unroll
            for (int i = 0; i < 4; i++) acc[mt][nt][i] = 0.f;

    uint32_t aadH[2], aadL[2], badH[4], badL[4];
    {
        int ar = (lane & 7) + ((lane >> 3) & 1) * 8;
        int ac = (lane >> 4) * 8;
        #pragma unroll
        for (int mt = 0; mt < 2; mt++) {
            int r = warpM * 32 + mt * 16 + ar;
            aadH[mt] = smem_u32(As_h) + (uint32_t)(r * SA + ac) * 2;
            aadL[mt] = smem_u32(As_l) + (uint32_t)(r * SA + ac) * 2;
        }
        int l16 = lane & 15;
        int bn = l16 & 7;
        int bc = ((l16 >> 3) & 1) * 8;
        #pragma unroll
        for (int nt = 0; nt < 4; nt++) {
            int n = warpN * 32 + nt * 8 + bn;
            badH[nt] = smem_u32(Bs_h) + (uint32_t)(n * SA + bc) * 2;
            badL[nt] = smem_u32(Bs_l) + (uint32_t)(n * SA + bc) * 2;
        }
    }

    for (int k0 = 0; k0 < K; k0 += 32) {
        #pragma unroll
        for (int it = 0; it < 2; it++) {
            int idx = tid + it * 256;
            int r = idx >> 2, sk = (idx & 3) * 8;
            int grow = row0 + r;
            uint4 vh = make_uint4(0, 0, 0, 0), vl = make_uint4(0, 0, 0, 0);
            if (grow < M) {
                size_t off = (size_t)grow * K + k0 + sk;
                vh = *(const uint4*)(Ahi + off);
                vl = *(const uint4*)(Alo + off);
            }
            *(uint4*)&As_h[r * SA + sk] = vh;
            *(uint4*)&As_l[r * SA + sk] = vl;
        }
        {
            int r = tid >> 2, sk = (tid & 3) * 8;
            size_t off = (size_t)(col0 + r) * K + k0 + sk;
            *(uint4*)&Bs_h[r * SA + sk] = *(const uint4*)(BhiT + off);
            *(uint4*)&Bs_l[r * SA + sk] = *(const uint4*)(BloT + off);
        }
        __syncthreads();

        #pragma unroll
        for (int ks = 0; ks < 32; ks += 16) {
            uint32_t kb = ks * 2;
            uint32_t ah[2][4], al[2][4], bh[4][2], bl[4][2];
            #pragma unroll
            for (int mt = 0; mt < 2; mt++) {
                LDSM_X4(ah[mt][0], ah[mt][1], ah[mt][2], ah[mt][3], aadH[mt] + kb);
                LDSM_X4(al[mt][0], al[mt][1], al[mt][2], al[mt][3], aadL[mt] + kb);
            }
            #pragma unroll
            for (int nt = 0; nt < 4; nt++) {
                LDSM_X2(bh[nt][0], bh[nt][1], badH[nt] + kb);
                LDSM_X2(bl[nt][0], bl[nt][1], badL[nt] + kb);
            }
            #pragma unroll
            for (int mt = 0; mt < 2; mt++)
                #pragma unroll
                for (int nt = 0; nt < 4; nt++) {
                    mma_bf16(acc[mt][nt], ah[mt][0], ah[mt][1], ah[mt][2], ah[mt][3],
                             bl[nt][0], bl[nt][1]);
                    mma_bf16(acc[mt][nt], al[mt][0], al[mt][1], al[mt][2], al[mt][3],
                             bh[nt][0], bh[nt][1]);
                    mma_bf16(acc[mt][nt], ah[mt][0], ah[mt][1], ah[mt][2], ah[mt][3],
                             bh[nt][0], bh[nt][1]);
                }
        }
        __syncthreads();
    }

    int g = lane >> 2, tg = lane & 3;
    #pragma unroll
    for (int nt = 0; nt < 4; nt++) {
        int col = col0 + warpN * 32 + nt * 8 + 2 * tg;
        float2 bv = *(const float2*)(bias + col);
        #pragma unroll
        for (int mt = 0; mt < 2; mt++) {
            int r = row0 + warpM * 32 + mt * 16 + g;
            if (r < M) {
                float2 v = make_float2(acc[mt][nt][0] + bv.x, acc[mt][nt][1] + bv.y);
                *(float2*)(C + (size_t)r * Ncols + col) = v;
            }
            if (r + 8 < M) {
                float2 v = make_float2(acc[mt][nt][2] + bv.x, acc[mt][nt][3] + bv.y);
                *(float2*)(C + (size_t)(r + 8) * Ncols + col) = v;
            }
        }
    }
}

// ---------------- fused edge aggregation, H=4: ONE warp per node, value-pipelined --
// lane owns 8 contiguous channels; per-head 3-SHFL butterfly. 2-edge stages with
// full rotation: while computing stage k, the xl values AND indices of stage k+1
// are already in flight.
__global__ void edge_agg_h4(const int* __restrict__ rowptr, const int* __restrict__ csr_src,
                            const float4* __restrict__ csr_ea,
                            const float* __restrict__ xl, const float* __restrict__ xr,
                            const float* __restrict__ We, const float* __restrict__ att,
                            const float* __restrict__ bias,
                            __nv_bfloat16* __restrict__ out_hi,
                            __nv_bfloat16* __restrict__ out_lo) {
    int w = (blockIdx.x * blockDim.x + threadIdx.x) >> 5;  // node
    int lane = threadIdx.x & 31;
    if (w >= N_NODES) return;
    int n = w;
    int c = lane * 8;

    float xrv[8], atv[8], wev[4][8];
    {
        float4 v0 = *(const float4*)(xr + (size_t)n * 256 + c);
        float4 v1 = *(const float4*)(xr + (size_t)n * 256 + c + 4);
        xrv[0] = v0.x; xrv[1] = v0.y; xrv[2] = v0.z; xrv[3] = v0.w;
        xrv[4] = v1.x; xrv[5] = v1.y; xrv[6] = v1.z; xrv[7] = v1.w;
        v0 = *(const float4*)(att + c);
        v1 = *(const float4*)(att + c + 4);
        atv[0] = v0.x; atv[1] = v0.y; atv[2] = v0.z; atv[3] = v0.w;
        atv[4] = v1.x; atv[5] = v1.y; atv[6] = v1.z; atv[7] = v1.w;
        #pragma unroll
        for (int f = 0; f < 4; f++) {
            v0 = *(const float4*)(We + f * 256 + c);
            v1 = *(const float4*)(We + f * 256 + c + 4);
            wev[f][0] = v0.x; wev[f][1] = v0.y; wev[f][2] = v0.z; wev[f][3] = v0.w;
            wev[f][4] = v1.x; wev[f][5] = v1.y; wev[f][6] = v1.z; wev[f][7] = v1.w;
        }
    }

    float s = 0.f, a[8];
    #pragma unroll
    for (int j = 0; j < 8; j++) a[j] = 0.f;
    int beg = rowptr[n], end = rowptr[n + 1];

    // pipeline state: current stage's values
    float4 ce0 = make_float4(0, 0, 0, 0), ce1 = ce0;
    float4 xa0 = ce0, xb0 = ce0, xa1 = ce0, xb1 = ce0;
    if (beg + 1 < end) {
        int s0i = csr_src[beg], s1i = csr_src[beg + 1];
        ce0 = csr_ea[beg];
        ce1 = csr_ea[beg + 1];
        xa0 = *(const float4*)(xl + (size_t)s0i * 256 + c);
        xb0 = *(const float4*)(xl + (size_t)s0i * 256 + c + 4);
        xa1 = *(const float4*)(xl + (size_t)s1i * 256 + c);
        xb1 = *(const float4*)(xl + (size_t)s1i * 256 + c + 4);
    }

    int i = beg;
    for (; i + 1 < end; i += 2) {
        // issue next stage's loads before computing current stage
        float4 ne0 = ce0, ne1 = ce1, nxa0 = xa0, nxb0 = xb0, nxa1 = xa1, nxb1 = xb1;
        if (i + 3 < end) {
            int s0i = csr_src[i + 2], s1i = csr_src[i + 3];
            ne0 = csr_ea[i + 2];
            ne1 = csr_ea[i + 3];
            nxa0 = *(const float4*)(xl + (size_t)s0i * 256 + c);
            nxb0 = *(const float4*)(xl + (size_t)s0i * 256 + c + 4);
            nxa1 = *(const float4*)(xl + (size_t)s1i * 256 + c);
            nxb1 = *(const float4*)(xl + (size_t)s1i * 256 + c + 4);
        }

        float x0[8] = {xa0.x, xa0.y, xa0.z, xa0.w, xb0.x, xb0.y, xb0.z, xb0.w};
        float x1[8] = {xa1.x, xa1.y, xa1.z, xa1.w, xb1.x, xb1.y, xb1.z, xb1.w};
        float t0 = 0.f, t1 = 0.f;
        #pragma unroll
        for (int j = 0; j < 8; j++) {
            float z0 = x0[j] + xrv[j] + ce0.x * wev[0][j] + ce0.y * wev[1][j]
                       + ce0.z * wev[2][j] + ce0.w * wev[3][j];
            float z1 = x1[j] + xrv[j] + ce1.x * wev[0][j] + ce1.y * wev[1][j]
                       + ce1.z * wev[2][j] + ce1.w * wev[3][j];
            z0 = z0 > 0.f ? z0 : 0.2f * z0;
            z1 = z1 > 0.f ? z1 : 0.2f * z1;
            t0 += z0 * atv[j];
            t1 += z1 * atv[j];
        }
        #pragma unroll
        for (int o = 4; o > 0; o >>= 1) {
            t0 += __shfl_xor_sync(0xFFFFFFFFu, t0, o);
            t1 += __shfl_xor_sync(0xFFFFFFFFu, t1, o);
        }
        float p0 = __expf(t0), p1 = __expf(t1);
        s += p0 + p1;
        #pragma unroll
        for (int j = 0; j < 8; j++) a[j] += p0 * x0[j] + p1 * x1[j];

        ce0 = ne0; ce1 = ne1;
        xa0 = nxa0; xb0 = nxb0; xa1 = nxa1; xb1 = nxb1;
    }
    if (i < end) {
        int sn = csr_src[i];
        float4 eav = csr_ea[i];
        float4 xa = *(const float4*)(xl + (size_t)sn * 256 + c);
        float4 xb = *(const float4*)(xl + (size_t)sn * 256 + c + 4);
        float xv[8] = {xa.x, xa.y, xa.z, xa.w, xb.x, xb.y, xb.z, xb.w};
        float t = 0.f;
        #pragma unroll
        for (int j = 0; j < 8; j++) {
            float z = xv[j] + xrv[j] + eav.x * wev[0][j] + eav.y * wev[1][j]
                      + eav.z * wev[2][j] + eav.w * wev[3][j];
            z = z > 0.f ? z : 0.2f * z;
            t += z * atv[j];
        }
        #pragma unroll
        for (int o = 4; o > 0; o >>= 1) t += __shfl_xor_sync(0xFFFFFFFFu, t, o);
        float p = __expf(t);
        s += p;
        #pragma unroll
        for (int j = 0; j < 8; j++) a[j] += p * xv[j];
    }

    float inv = 1.f / (s + 1e-16f);
    float4 bv0 = *(const float4*)(bias + c);
    float4 bv1 = *(const float4*)(bias + c + 4);
    float bb[8] = {bv0.x, bv0.y, bv0.z, bv0.w, bv1.x, bv1.y, bv1.z, bv1.w};
    uint16_t hv[8], lv[8];
    #pragma unroll
    for (int j = 0; j < 8; j++) {
        float r = a[j] * inv + bb[j];
        r = r > 0.f ? r : expm1f(r);   // ELU
        __nv_bfloat16 h = __float2bfloat16(r);
        __nv_bfloat16 l = __float2bfloat16(r - __bfloat162float(h));
        hv[j] = *(uint16_t*)&h;
        lv[j] = *(uint16_t*)&l;
    }
    *(uint4*)(out_hi + (size_t)n * 256 + c) = *(uint4*)hv;
    *(uint4*)(out_lo + (size_t)n * 256 + c) = *(uint4*)lv;
}

// ---------------- edge aggregation, H=1 (layer 3) + fused global-mean-pool --------
__global__ void edge_agg_h1_pool(const int* __restrict__ rowptr, const int* __restrict__ csr_src,
                                 const float4* __restrict__ csr_ea,
                                 const float* __restrict__ xl, const float* __restrict__ xr,
                                 const float* __restrict__ We, const float* __restrict__ att,
                                 const float* __restrict__ bias, const int* __restrict__ batch,
                                 float* __restrict__ sums, int* __restrict__ cnt) {
    const int D = 64;
    int w = (blockIdx.x * blockDim.x + threadIdx.x) >> 5;
    int lane = threadIdx.x & 31;
    int n = w;
    if (n >= N_NODES) return;

    int c = 2 * lane;
    float2 xrv = *(const float2*)(xr + (size_t)n * D + c);
    float2 atv = *(const float2*)(att + c);
    float2 wev[4];
    #pragma unroll
    for (int f = 0; f < 4; f++) wev[f] = *(const float2*)(We + f * D + c);

    float s0 = 0.f, a00 = 0.f, a01 = 0.f;
    float s1 = 0.f, a10 = 0.f, a11 = 0.f;
    int beg = rowptr[n], end = rowptr[n + 1];

    int i = beg;
    for (; i + 3 < end; i += 4) {
        int sn0 = csr_src[i], sn1 = csr_src[i + 1], sn2 = csr_src[i + 2], sn3 = csr_src[i + 3];
        float4 e0 = csr_ea[i], e1 = csr_ea[i + 1], e2 = csr_ea[i + 2], e3 = csr_ea[i + 3];
        float2 x0 = *(const float2*)(xl + (size_t)sn0 * D + c);
        float2 x1 = *(const float2*)(xl + (size_t)sn1 * D + c);
        float2 x2 = *(const float2*)(xl + (size_t)sn2 * D + c);
        float2 x3 = *(const float2*)(xl + (size_t)sn3 * D + c);

        float za, zb, t0, t1, t2, t3;
        za = x0.x + xrv.x + e0.x * wev[0].x + e0.y * wev[1].x + e0.z * wev[2].x + e0.w * wev[3].x;
        zb = x0.y + xrv.y + e0.x * wev[0].y + e0.y * wev[1].y + e0.z * wev[2].y + e0.w * wev[3].y;
        za = za > 0.f ? za : 0.2f * za; zb = zb > 0.f ? zb : 0.2f * zb;
        t0 = za * atv.x + zb * atv.y;
        za = x1.x + xrv.x + e1.x * wev[0].x + e1.y * wev[1].x + e1.z * wev[2].x + e1.w * wev[3].x;
        zb = x1.y + xrv.y + e1.x * wev[0].y + e1.y * wev[1].y + e1.z * wev[2].y + e1.w * wev[3].y;
        za = za > 0.f ? za : 0.2f * za; zb = zb > 0.f ? zb : 0.2f * zb;
        t1 = za * atv.x + zb * atv.y;
        za = x2.x + xrv.x + e2.x * wev[0].x + e2.y * wev[1].x + e2.z * wev[2].x + e2.w * wev[3].x;
        zb = x2.y + xrv.y + e2.x * wev[0].y + e2.y * wev[1].y + e2.z * wev[2].y + e2.w * wev[3].y;
        za = za > 0.f ? za : 0.2f * za; zb = zb > 0.f ? zb : 0.2f * zb;
        t2 = za * atv.x + zb * atv.y;
        za = x3.x + xrv.x + e3.x * wev[0].x + e3.y * wev[1].x + e3.z * wev[2].x + e3.w * wev[3].x;
        zb = x3.y + xrv.y + e3.x * wev[0].y + e3.y * wev[1].y + e3.z * wev[2].y + e3.w * wev[3].y;
        za = za > 0.f ? za : 0.2f * za; zb = zb > 0.f ? zb : 0.2f * zb;
        t3 = za * atv.x + zb * atv.y;

        #pragma unroll
        for (int o = 16; o > 0; o >>= 1) {
            t0 += __shfl_xor_sync(0xFFFFFFFFu, t0, o);
            t1 += __shfl_xor_sync(0xFFFFFFFFu, t1, o);
            t2 += __shfl_xor_sync(0xFFFFFFFFu, t2, o);
            t3 += __shfl_xor_sync(0xFFFFFFFFu, t3, o);
        }
        float p0 = __expf(t0), p1 = __expf(t1), p2 = __expf(t2), p3 = __expf(t3);
        s0 += p0; a00 += p0 * x0.x; a01 += p0 * x0.y;
        s1 += p1; a10 += p1 * x1.x; a11 += p1 * x1.y;
        s0 += p2; a00 += p2 * x2.x; a01 += p2 * x2.y;
        s1 += p3; a10 += p3 * x3.x; a11 += p3 * x3.y;
    }
    for (; i < end; i++) {
        int sn = csr_src[i];
        float4 eav = csr_ea[i];
        float2 xv = *(const float2*)(xl + (size_t)sn * D + c);
        float z0 = xv.x + xrv.x + eav.x * wev[0].x + eav.y * wev[1].x + eav.z * wev[2].x + eav.w * wev[3].x;
        float z1 = xv.y + xrv.y + eav.x * wev[0].y + eav.y * wev[1].y + eav.z * wev[2].y + eav.w * wev[3].y;
        z0 = z0 > 0.f ? z0 : 0.2f * z0;
        z1 = z1 > 0.f ? z1 : 0.2f * z1;
        float t = z0 * atv.x + z1 * atv.y;
        #pragma unroll
        for (int o = 16; o > 0; o >>= 1) t += __shfl_xor_sync(0xFFFFFFFFu, t, o);
        float p = __expf(t);
        s0 += p; a00 += p * xv.x; a01 += p * xv.y;
    }
    float s = s0 + s1;
    float a0 = a00 + a10;
    float a1 = a01 + a11;

    float inv = 1.f / (s + 1e-16f);
    float2 bv = *(const float2*)(bias + c);
    float r0 = a0 * inv + bv.x;
    float r1 = a1 * inv + bv.y;

    int g = batch[n];
    atomicAdd(&sums[g * 64 + c], r0);
    atomicAdd(&sums[g * 64 + c + 1], r1);
    if (lane == 0) atomicAdd(&cnt[g], 1);
}

// ---------------- MLP head ----------------
__global__ void mlp_k(const float* __restrict__ sums, const int* __restrict__ cnt,
                      const float* __restrict__ mW1, const float* __restrict__ mb1,
                      const float* __restrict__ mW2, const float* __restrict__ mb2,
                      const float* __restrict__ mW3, const float* __restrict__ mb3,
                      float* __restrict__ out) {
    __shared__ float gv[64];
    __shared__ float h1[32];
    __shared__ float h2[16];
    int g = blockIdx.x, t = threadIdx.x;
    float cf = fmaxf((float)cnt[g], 1.f);
    gv[t] = sums[g * 64 + t] / cf;
    __syncthreads();
    if (t < 32) {
        float a = mb1[t];
        #pragma unroll
        for (int k = 0; k < 64; k++) a += gv[k] * mW1[k * 32 + t];
        h1[t] = fmaxf(a, 0.f);
    }
    __syncthreads();
    if (t < 16) {
        float a = mb2[t];
        #pragma unroll
        for (int k = 0; k < 32; k++) a += h1[k] * mW2[k * 16 + t];
        h2[t] = fmaxf(a, 0.f);
    }
    __syncthreads();
    if (t < 4) {
        float a = mb3[t];
        #pragma unroll
        for (int k = 0; k < 16; k++) a += h2[k] * mW3[k * 4 + t];
        out[g * 4 + t] = a;
    }
}

// ---------------- launch ----------------
extern "C" void kernel_launch(void* const* d_in, const int* in_sizes, int n_in,
                              void* d_out, int out_size) {
    (void)in_sizes; (void)n_in; (void)out_size;
    const float* x     = (const float*)d_in[0];
    const int*   ei    = (const int*)d_in[1];
    const float* ea    = (const float*)d_in[2];
    const int*   batch = (const int*)d_in[3];
    const float* Wl1 = (const float*)d_in[4],  *bl1 = (const float*)d_in[5];
    const float* Wr1 = (const float*)d_in[6],  *br1 = (const float*)d_in[7];
    const float* We1 = (const float*)d_in[8],  *att1 = (const float*)d_in[9],  *bias1 = (const float*)d_in[10];
    const float* Wl2 = (const float*)d_in[11], *bl2 = (const float*)d_in[12];
    const float* Wr2 = (const float*)d_in[13], *br2 = (const float*)d_in[14];
    const float* We2 = (const float*)d_in[15], *att2 = (const float*)d_in[16], *bias2 = (const float*)d_in[17];
    const float* Wl3 = (const float*)d_in[18], *bl3 = (const float*)d_in[19];
    const float* Wr3 = (const float*)d_in[20], *br3 = (const float*)d_in[21];
    const float* We3 = (const float*)d_in[22], *att3 = (const float*)d_in[23], *bias3 = (const float*)d_in[24];
    const float* mW1 = (const float*)d_in[25], *mb1 = (const float*)d_in[26];
    const float* mW2 = (const float*)d_in[27], *mb2 = (const float*)d_in[28];
    const float* mW3 = (const float*)d_in[29], *mb3 = (const float*)d_in[30];
    float* out = (float*)d_out;

    const int* srcp = ei;
    const int* dstp = ei + N_EDGES;

    float *xl, *xr, *sums;
    int *deg, *rowptr, *cursor, *csr_src, *cnt;
    float4* csr_ea;
    __nv_bfloat16 *ahi, *alo, *whL, *wlL, *whR, *wlR;
    cudaGetSymbolAddress((void**)&xl, g_xl);
    cudaGetSymbolAddress((void**)&xr, g_xr);
    cudaGetSymbolAddress((void**)&sums, g_sums);
    cudaGetSymbolAddress((void**)&deg, g_deg);
    cudaGetSymbolAddress((void**)&rowptr, g_rowptr);
    cudaGetSymbolAddress((void**)&cursor, g_cursor);
    cudaGetSymbolAddress((void**)&csr_src, g_csr_src);
    cudaGetSymbolAddress((void**)&csr_ea, g_csr_ea);
    cudaGetSymbolAddress((void**)&cnt, g_cnt);
    cudaGetSymbolAddress((void**)&ahi, g_ahi);
    cudaGetSymbolAddress((void**)&alo, g_alo);
    cudaGetSymbolAddress((void**)&whL, g_whL);
    cudaGetSymbolAddress((void**)&wlL, g_wlL);
    cudaGetSymbolAddress((void**)&whR, g_whR);
    cudaGetSymbolAddress((void**)&wlR, g_wlR);

    // launches 1-4: CSR by destination (shared by all 3 layers)
    zero_i32<<<(N_NODES + 255) / 256, 256>>>(deg, N_NODES);
    hist_k<<<(N_EDGES + 255) / 256, 256>>>(dstp, deg);
    scan_k<<<1, 1024>>>(deg, rowptr, cursor);
    scatter_k<<<(N_EDGES + 255) / 256, 256>>>(srcp, dstp, (const float4*)ea, cursor, csr_src, csr_ea);

    // launch 5: layer-1 dual GEMM (xl + xr in one pass)
    gemm_k12_dual<<<(N_NODES + 31) / 32, 256>>>(x, Wl1, bl1, Wr1, br1, xl, xr);

    // launch 6: edge_agg_h4 — profiled by ncu (-s 5 -c 1)
    edge_agg_h4<<<2500, 256>>>(rowptr, csr_src, csr_ea, xl, xr, We1, att1, bias1, ahi, alo);

    // ---- layer 2 (256 -> 256, H=4): one dual launch for L+R ----
    splitW_dual<<<(256 * 256 + 255) / 256, 256>>>(Wl2, Wr2, whL, wlL, whR, wlR, 256, 256);
    gemm_bf16_dual<<<dim3(4, 157, 2), 256>>>(ahi, alo, whL, wlL, whR, wlR, bl2, br2,
                                             xl, xr, N_NODES, 256, 256);
    edge_agg_h4<<<2500, 256>>>(rowptr, csr_src, csr_ea, xl, xr, We2, att2, bias2, ahi, alo);

    // ---- layer 3 (256 -> 64, H=1, no ELU), pool fused into epilogue ----
    splitW_dual<<<(256 * 64 + 255) / 256, 256>>>(Wl3, Wr3, whL, wlL, whR, wlR, 256, 64);
    gemm_bf16_dual<<<dim3(1, 157, 2), 256>>>(ahi, alo, whL, wlL, whR, wlR, bl3, br3,
                                             xl, xr, N_NODES, 256, 64);
    zero_f32<<<(N_GRAPHS * 64 + 255) / 256, 256>>>(sums, N_GRAPHS * 64);
    zero_i32<<<(N_GRAPHS + 255) / 256, 256>>>(cnt, N_GRAPHS);
    edge_agg_h1_pool<<<2500, 256>>>(rowptr, csr_src, csr_ea, xl, xr, We3, att3, bias3,
                                    batch, sums, cnt);

    // ---- MLP head ----
    mlp_k<<<N_GRAPHS, 64>>>(sums, cnt, mW1, mb1, mW2, mb2, mW3, mb3, out);
}